// round 12
// baseline (speedup 1.0000x reference)
#include <cuda_runtime.h>
#include <cuda_bf16.h>
#include <math.h>
#include <stdint.h>

#define BATCH 4
#define SEQ 2048
#define DM 512
#define NH 8
#define HD 64
#define ROWS (BATCH*SEQ)
#define RPE_LEN (2*SEQ-1)

// Scratch (static __device__ — no allocations allowed)
__device__ float g_q[BATCH*NH*SEQ*HD];
__device__ float g_k[BATCH*NH*SEQ*HD];
__device__ float g_v[BATCH*NH*SEQ*HD];
__device__ float g_o[BATCH*SEQ*DM];
__device__ float g_sig[NH*RPE_LEN];
__device__ float g_scale[NH];

// ===========================================================================
// mma.sync bf16 helpers (compute_103-safe: sm_80+ instructions only)
// ===========================================================================
__device__ __forceinline__ void mma_bf16(float d[4], const uint32_t a[4],
                                         const uint32_t b[2]) {
    asm volatile(
        "mma.sync.aligned.m16n8k16.row.col.f32.bf16.bf16.f32 "
        "{%0,%1,%2,%3}, {%4,%5,%6,%7}, {%8,%9}, {%0,%1,%2,%3};"
        : "+f"(d[0]), "+f"(d[1]), "+f"(d[2]), "+f"(d[3])
        : "r"(a[0]), "r"(a[1]), "r"(a[2]), "r"(a[3]), "r"(b[0]), "r"(b[1]));
}

// pack two f32 into bf16x2 (x0 -> low half, x1 -> high half)
__device__ __forceinline__ uint32_t pack2bf(float x0, float x1) {
    uint32_t r;
    asm("cvt.rn.bf16x2.f32 %0, %1, %2;" : "=r"(r) : "f"(x1), "f"(x0));
    return r;
}

// split (x0,x1) into hi bf16x2 + residual-lo bf16x2
__device__ __forceinline__ void split2(float x0, float x1,
                                       uint32_t& hp, uint32_t& lp) {
    hp = pack2bf(x0, x1);
    float h0 = __uint_as_float(hp << 16);
    float h1 = __uint_as_float(hp & 0xFFFF0000u);
    lp = pack2bf(x0 - h0, x1 - h1);
}

#define LDT 72          // bf16 tile row stride (64 + 8 pad): conflict-free frags
#define CS_LD 130       // f32 epilogue staging stride

// GEMM smem layout (bytes)
#define OF_BIAS 0
#define OF_T    512
#define T_A_HI  (OF_T)
#define T_A_LO  (OF_T + 18432)
#define T_B_HI  (OF_T + 36864)
#define T_B_LO  (OF_T + 55296)
#define GEMM_SMEM_BYTES (512 + 4*18432)      // 74240; Cs (66560) aliases tiles

// ---------------------------------------------------------------------------
// Kernel 1: precompute sigmoid(rpe) + per-head scale
// ---------------------------------------------------------------------------
__global__ void prep_kernel(const float* __restrict__ rpe,
                            const float* __restrict__ ls) {
    int i = blockIdx.x * blockDim.x + threadIdx.x;
    if (i < NH * RPE_LEN) {
        int hh = i % NH;
        int p  = i / NH;
        float x = rpe[p * NH + hh];
        g_sig[hh * RPE_LEN + p] = 1.0f / (1.0f + __expf(-x));
    }
    if (i < NH) g_scale[i] = __expf(fminf(ls[i], 4.6051701859880914f));
}

// ---------------------------------------------------------------------------
// Shared 128x128 GEMM tile via mma.sync, split-bf16 fp32 emulation.
// C = A(128 x 512) * B(128 rows x 512)^T, both fp32 row-major ld=512.
// Result staged into Cs[col*CS_LD + row] (Cs aliases tile smem).
// 256 threads = 8 warps in 2(m) x 4(n); warp tile 64x32.
// ---------------------------------------------------------------------------
__device__ __forceinline__ void gemm_tile(const float* __restrict__ A,
                                          const float* __restrict__ B,
                                          char* sm, int tid, float* Cs) {
    const int wid = tid >> 5, lane = tid & 31;
    const int gr = lane >> 2, tg = lane & 3;
    const int wm = (wid >> 2) * 64;
    const int wn = (wid & 3) * 32;

    __nv_bfloat16* Ahi = (__nv_bfloat16*)(sm + T_A_HI);
    __nv_bfloat16* Alo = (__nv_bfloat16*)(sm + T_A_LO);
    __nv_bfloat16* Bhi = (__nv_bfloat16*)(sm + T_B_HI);
    __nv_bfloat16* Blo = (__nv_bfloat16*)(sm + T_B_LO);

    float acc[4][4][4] = {};

    for (int c = 0; c < 8; ++c) {
        const int k0 = c * 64;
        // fp32 -> (hi, lo) bf16 conversion into padded smem tiles
#pragma unroll
        for (int it = 0; it < 16; ++it) {
            int id  = it * 256 + tid;
            int mat = id >> 11;
            int rr  = (id >> 4) & 127;
            int gg  = id & 15;
            const float* src = (mat ? B : A) + (size_t)rr * DM + k0 + gg * 4;
            float4 f = *(const float4*)src;
            uint32_t h0, l0, h1, l1;
            split2(f.x, f.y, h0, l0);
            split2(f.z, f.w, h1, l1);
            int off = rr * LDT + gg * 4;
            *(uint2*)((mat ? Bhi : Ahi) + off) = make_uint2(h0, h1);
            *(uint2*)((mat ? Blo : Alo) + off) = make_uint2(l0, l1);
        }
        __syncthreads();

#pragma unroll
        for (int ks = 0; ks < 4; ++ks) {
            const int cc = ks * 16 + tg * 2;
            uint32_t ahi[4][4], alo[4][4];
#pragma unroll
            for (int mt = 0; mt < 4; ++mt) {
                int r0 = wm + mt * 16 + gr;
                ahi[mt][0] = *(const uint32_t*)(Ahi + r0 * LDT + cc);
                ahi[mt][1] = *(const uint32_t*)(Ahi + (r0 + 8) * LDT + cc);
                ahi[mt][2] = *(const uint32_t*)(Ahi + r0 * LDT + cc + 8);
                ahi[mt][3] = *(const uint32_t*)(Ahi + (r0 + 8) * LDT + cc + 8);
                alo[mt][0] = *(const uint32_t*)(Alo + r0 * LDT + cc);
                alo[mt][1] = *(const uint32_t*)(Alo + (r0 + 8) * LDT + cc);
                alo[mt][2] = *(const uint32_t*)(Alo + r0 * LDT + cc + 8);
                alo[mt][3] = *(const uint32_t*)(Alo + (r0 + 8) * LDT + cc + 8);
            }
#pragma unroll
            for (int nt = 0; nt < 4; ++nt) {
                int n0 = wn + nt * 8 + gr;
                uint32_t bhi[2] = {
                    *(const uint32_t*)(Bhi + n0 * LDT + cc),
                    *(const uint32_t*)(Bhi + n0 * LDT + cc + 8)};
                uint32_t blo[2] = {
                    *(const uint32_t*)(Blo + n0 * LDT + cc),
                    *(const uint32_t*)(Blo + n0 * LDT + cc + 8)};
#pragma unroll
                for (int mt = 0; mt < 4; ++mt) {
                    mma_bf16(acc[mt][nt], ahi[mt], bhi);
                    mma_bf16(acc[mt][nt], ahi[mt], blo);
                    mma_bf16(acc[mt][nt], alo[mt], bhi);
                }
            }
        }
        __syncthreads();
    }

    // stage C into Cs[col][row] (aliases tiles; guarded by the sync above)
#pragma unroll
    for (int mt = 0; mt < 4; ++mt)
#pragma unroll
        for (int nt = 0; nt < 4; ++nt) {
            int r  = wm + mt * 16 + gr;
            int cl = wn + nt * 8 + tg * 2;
            Cs[cl * CS_LD + r]           = acc[mt][nt][0];
            Cs[(cl + 1) * CS_LD + r]     = acc[mt][nt][1];
            Cs[cl * CS_LD + r + 8]       = acc[mt][nt][2];
            Cs[(cl + 1) * CS_LD + r + 8] = acc[mt][nt][3];
        }
    __syncthreads();
}

// ---------------------------------------------------------------------------
// Kernel 2: QKV projections. grid = (64, 4, 3), block 256.
// ---------------------------------------------------------------------------
__global__ __launch_bounds__(256) void qkv_mm_kernel(
    const float* __restrict__ X,
    const float* __restrict__ Wq, const float* __restrict__ bq,
    const float* __restrict__ Wk, const float* __restrict__ bk,
    const float* __restrict__ Wv, const float* __restrict__ bv) {
    extern __shared__ char sm[];
    const int tid = threadIdx.x;
    const int row0 = blockIdx.x * 128;
    const int n0   = blockIdx.y * 128;
    const int which = blockIdx.z;
    const float* W    = (which == 0) ? Wq : (which == 1) ? Wk : Wv;
    const float* bias = (which == 0) ? bq : (which == 1) ? bk : bv;
    float* out        = (which == 0) ? g_q : (which == 1) ? g_k : g_v;

    float* bsm = (float*)(sm + OF_BIAS);
    if (tid < 128) bsm[tid] = bias[n0 + tid];

    float* Cs = (float*)(sm + OF_T);
    gemm_tile(X + (size_t)row0 * DM, W + (size_t)n0 * DM, sm, tid, Cs);

    const int d0base = n0 >> 3;
#pragma unroll
    for (int it = 0; it < 16; ++it) {
        int id  = it * 256 + tid;
        int g   = id & 3;
        int h   = (id >> 2) & 7;
        int row = id >> 5;
        float v[4];
#pragma unroll
        for (int u = 0; u < 4; ++u) {
            int j = h + 32 * g + 8 * u;
            v[u] = Cs[j * CS_LD + row] + bsm[j];
        }
        int r = row0 + row;
        int b = r >> 11;
        int s = r & (SEQ - 1);
        int d0 = d0base + 4 * g;
        *(float4*)(out + ((size_t)((b * NH + h) * SEQ + s)) * HD + d0) =
            make_float4(v[0], v[1], v[2], v[3]);
    }
}

// ---------------------------------------------------------------------------
// Kernel 4: output projection. grid = (64, 4), block 256.
// ---------------------------------------------------------------------------
__global__ __launch_bounds__(256) void oproj_mm_kernel(
    const float* __restrict__ Wp, const float* __restrict__ bp,
    float* __restrict__ out) {
    extern __shared__ char sm[];
    const int tid = threadIdx.x;
    const int row0 = blockIdx.x * 128;
    const int n0   = blockIdx.y * 128;

    float* bsm = (float*)(sm + OF_BIAS);
    if (tid < 128) bsm[tid] = bp[n0 + tid];

    float* Cs = (float*)(sm + OF_T);
    gemm_tile(g_o + (size_t)row0 * DM, Wp + (size_t)n0 * DM, sm, tid, Cs);

#pragma unroll
    for (int it = 0; it < 16; ++it) {
        int id  = it * 256 + tid;
        int q4  = id & 31;
        int row = id >> 5;
        float v[4];
#pragma unroll
        for (int u = 0; u < 4; ++u) {
            int j = 4 * q4 + u;
            v[u] = Cs[j * CS_LD + row] + bsm[j];
        }
        *(float4*)(out + (size_t)(row0 + row) * DM + n0 + 4 * q4) =
            make_float4(v[0], v[1], v[2], v[3]);
    }
}

// ---------------------------------------------------------------------------
// Kernel 3: flash attention via mma.sync. grid = (16, 32), block 256.
// 128 Q-rows per CTA (warp = 16 rows), 64-key tiles, split-bf16 everywhere.
// smem: Khi@0 Klo@9216 Vthi@18432 Vtlo@27648 (each 64*72*2B), sg@36864.
// Q staging reuses bytes [0, 36864).
// ---------------------------------------------------------------------------
#define ALDT 72
#define ATTN_SMEM_BYTES (36864 + 768)

__global__ __launch_bounds__(256) void attn_mm_kernel() {
    extern __shared__ char sm[];
    const int tid = threadIdx.x, wid = tid >> 5, lane = tid & 31;
    const int gr = lane >> 2, tg = lane & 3;
    const int bh = blockIdx.y, b = bh >> 3, h = bh & 7;
    const int q0 = blockIdx.x * 128;
    const float* Q = g_q + (size_t)bh * SEQ * HD;
    const float* K = g_k + (size_t)bh * SEQ * HD;
    const float* V = g_v + (size_t)bh * SEQ * HD;
    const float cscale = g_scale[h] * 0.04419417382415922f;  // 1/sqrt(512)

    // ---- stage Q (fp32 -> split bf16), then lift fragments to registers
    __nv_bfloat16* Qhi = (__nv_bfloat16*)sm;
    __nv_bfloat16* Qlo = (__nv_bfloat16*)(sm + 18432);
#pragma unroll
    for (int it = 0; it < 8; ++it) {
        int id = it * 256 + tid;
        int rr = id >> 4, gg = id & 15;
        float4 f = *(const float4*)(Q + (size_t)(q0 + rr) * HD + gg * 4);
        uint32_t h0, l0, h1, l1;
        split2(f.x, f.y, h0, l0);
        split2(f.z, f.w, h1, l1);
        *(uint2*)(Qhi + rr * ALDT + gg * 4) = make_uint2(h0, h1);
        *(uint2*)(Qlo + rr * ALDT + gg * 4) = make_uint2(l0, l1);
    }
    __syncthreads();

    uint32_t qhi[4][4], qlo[4][4];
    {
        int r0 = wid * 16 + gr;
#pragma unroll
        for (int ks = 0; ks < 4; ++ks) {
            int cc = ks * 16 + tg * 2;
            qhi[ks][0] = *(uint32_t*)(Qhi + r0 * ALDT + cc);
            qhi[ks][1] = *(uint32_t*)(Qhi + (r0 + 8) * ALDT + cc);
            qhi[ks][2] = *(uint32_t*)(Qhi + r0 * ALDT + cc + 8);
            qhi[ks][3] = *(uint32_t*)(Qhi + (r0 + 8) * ALDT + cc + 8);
            qlo[ks][0] = *(uint32_t*)(Qlo + r0 * ALDT + cc);
            qlo[ks][1] = *(uint32_t*)(Qlo + (r0 + 8) * ALDT + cc);
            qlo[ks][2] = *(uint32_t*)(Qlo + r0 * ALDT + cc + 8);
            qlo[ks][3] = *(uint32_t*)(Qlo + (r0 + 8) * ALDT + cc + 8);
        }
    }
    __syncthreads();   // Q staging region is about to be reused for K/V

    __nv_bfloat16* Khi  = (__nv_bfloat16*)sm;
    __nv_bfloat16* Klo  = (__nv_bfloat16*)(sm + 9216);
    __nv_bfloat16* Vthi = (__nv_bfloat16*)(sm + 18432);
    __nv_bfloat16* Vtlo = (__nv_bfloat16*)(sm + 27648);
    float* sg = (float*)(sm + 36864);

    float m0r = -1e30f, m1r = -1e30f, l0r = 0.0f, l1r = 0.0f;
    float Oa[8][4] = {};
    const int qi0 = wid * 16 + gr;   // local q row of c0/c1

    for (int kt = 0; kt < 32; ++kt) {
        const int k0 = kt * 64;
        // ---- convert K [key][d] and V -> Vt [d][key] tiles
#pragma unroll
        for (int it = 0; it < 4; ++it) {
            int id = it * 256 + tid;
            int kk = id >> 4, gg = id & 15;
            float4 f = *(const float4*)(K + (size_t)(k0 + kk) * HD + gg * 4);
            uint32_t h0, l0, h1, l1;
            split2(f.x, f.y, h0, l0);
            split2(f.z, f.w, h1, l1);
            *(uint2*)(Khi + kk * ALDT + gg * 4) = make_uint2(h0, h1);
            *(uint2*)(Klo + kk * ALDT + gg * 4) = make_uint2(l0, l1);
            float4 fv = *(const float4*)(V + (size_t)(k0 + kk) * HD + gg * 4);
            float xs[4] = {fv.x, fv.y, fv.z, fv.w};
#pragma unroll
            for (int u = 0; u < 4; ++u) {
                int d = gg * 4 + u;
                __nv_bfloat16 hb = __float2bfloat16(xs[u]);
                Vthi[d * ALDT + kk] = hb;
                Vtlo[d * ALDT + kk] =
                    __float2bfloat16(xs[u] - __bfloat162float(hb));
            }
        }
        if (tid < 191)
            sg[tid] = g_sig[h * RPE_LEN + (q0 - k0 + 1984) + tid];
        __syncthreads();

        // ---- S = Q K^T (8 n-tiles of 8 keys)
        float p[8][4];
#pragma unroll
        for (int nt = 0; nt < 8; ++nt) {
            p[nt][0] = p[nt][1] = p[nt][2] = p[nt][3] = 0.0f;
            int n0 = nt * 8 + gr;
#pragma unroll
            for (int ks = 0; ks < 4; ++ks) {
                int cc = ks * 16 + tg * 2;
                uint32_t bhi[2] = {*(uint32_t*)(Khi + n0 * ALDT + cc),
                                   *(uint32_t*)(Khi + n0 * ALDT + cc + 8)};
                uint32_t blo[2] = {*(uint32_t*)(Klo + n0 * ALDT + cc),
                                   *(uint32_t*)(Klo + n0 * ALDT + cc + 8)};
                mma_bf16(p[nt], qhi[ks], bhi);
                mma_bf16(p[nt], qhi[ks], blo);
                mma_bf16(p[nt], qlo[ks], bhi);
            }
        }

        // ---- scale + RPE bias + online softmax
        float rmax0 = -1e30f, rmax1 = -1e30f;
#pragma unroll
        for (int nt = 0; nt < 8; ++nt) {
            int kj = nt * 8 + tg * 2;
            p[nt][0] = p[nt][0] * cscale + sg[qi0 - kj + 63];
            p[nt][1] = p[nt][1] * cscale + sg[qi0 - kj + 62];
            p[nt][2] = p[nt][2] * cscale + sg[qi0 - kj + 71];
            p[nt][3] = p[nt][3] * cscale + sg[qi0 - kj + 70];
            rmax0 = fmaxf(rmax0, fmaxf(p[nt][0], p[nt][1]));
            rmax1 = fmaxf(rmax1, fmaxf(p[nt][2], p[nt][3]));
        }
#pragma unroll
        for (int off = 1; off <= 2; off <<= 1) {
            rmax0 = fmaxf(rmax0, __shfl_xor_sync(0xffffffffu, rmax0, off));
            rmax1 = fmaxf(rmax1, __shfl_xor_sync(0xffffffffu, rmax1, off));
        }
        float mn0 = fmaxf(m0r, rmax0), mn1 = fmaxf(m1r, rmax1);
        float al0 = __expf(m0r - mn0), al1 = __expf(m1r - mn1);
        float rs0 = 0.0f, rs1 = 0.0f;
#pragma unroll
        for (int nt = 0; nt < 8; ++nt) {
            p[nt][0] = __expf(p[nt][0] - mn0);
            p[nt][1] = __expf(p[nt][1] - mn0);
            p[nt][2] = __expf(p[nt][2] - mn1);
            p[nt][3] = __expf(p[nt][3] - mn1);
            rs0 += p[nt][0] + p[nt][1];
            rs1 += p[nt][2] + p[nt][3];
        }
#pragma unroll
        for (int off = 1; off <= 2; off <<= 1) {
            rs0 += __shfl_xor_sync(0xffffffffu, rs0, off);
            rs1 += __shfl_xor_sync(0xffffffffu, rs1, off);
        }
        l0r = l0r * al0 + rs0;
        l1r = l1r * al1 + rs1;
        m0r = mn0;
        m1r = mn1;
#pragma unroll
        for (int nt = 0; nt < 8; ++nt) {
            Oa[nt][0] *= al0; Oa[nt][1] *= al0;
            Oa[nt][2] *= al1; Oa[nt][3] *= al1;
        }

        // ---- pack P into A-fragments (register-only, split hi/lo)
        uint32_t phi[4][4], plo[4][4];
#pragma unroll
        for (int ks2 = 0; ks2 < 4; ++ks2) {
            int ntA = 2 * ks2, ntB = 2 * ks2 + 1;
            split2(p[ntA][0], p[ntA][1], phi[ks2][0], plo[ks2][0]);
            split2(p[ntA][2], p[ntA][3], phi[ks2][1], plo[ks2][1]);
            split2(p[ntB][0], p[ntB][1], phi[ks2][2], plo[ks2][2]);
            split2(p[ntB][2], p[ntB][3], phi[ks2][3], plo[ks2][3]);
        }

        // ---- O += P V
#pragma unroll
        for (int nt = 0; nt < 8; ++nt) {
            int n0 = nt * 8 + gr;
#pragma unroll
            for (int ks2 = 0; ks2 < 4; ++ks2) {
                int cc = ks2 * 16 + tg * 2;
                uint32_t vhi[2] = {*(uint32_t*)(Vthi + n0 * ALDT + cc),
                                   *(uint32_t*)(Vthi + n0 * ALDT + cc + 8)};
                uint32_t vlo[2] = {*(uint32_t*)(Vtlo + n0 * ALDT + cc),
                                   *(uint32_t*)(Vtlo + n0 * ALDT + cc + 8)};
                mma_bf16(Oa[nt], phi[ks2], vhi);
                mma_bf16(Oa[nt], phi[ks2], vlo);
                mma_bf16(Oa[nt], plo[ks2], vhi);
            }
        }
        __syncthreads();
    }

    // ---- normalize, write concat-head layout col = h*64 + d
    float inv0 = 1.0f / l0r, inv1 = 1.0f / l1r;
    int qrow = q0 + qi0;
#pragma unroll
    for (int nt = 0; nt < 8; ++nt) {
        int col = h * HD + nt * 8 + tg * 2;
        *(float2*)(g_o + (size_t)(b * SEQ + qrow) * DM + col) =
            make_float2(Oa[nt][0] * inv0, Oa[nt][1] * inv0);
        *(float2*)(g_o + (size_t)(b * SEQ + qrow + 8) * DM + col) =
            make_float2(Oa[nt][2] * inv1, Oa[nt][3] * inv1);
    }
}

// ---------------------------------------------------------------------------
extern "C" void kernel_launch(void* const* d_in, const int* in_sizes, int n_in,
                              void* d_out, int out_size) {
    (void)in_sizes; (void)n_in; (void)out_size;
    const float* query = (const float*)d_in[0];
    const float* Wq = (const float*)d_in[1];
    const float* bq = (const float*)d_in[2];
    const float* Wk = (const float*)d_in[3];
    const float* bk = (const float*)d_in[4];
    const float* Wv = (const float*)d_in[5];
    const float* bv = (const float*)d_in[6];
    const float* Wp = (const float*)d_in[7];
    const float* bp = (const float*)d_in[8];
    const float* ls = (const float*)d_in[9];
    const float* rpe = (const float*)d_in[10];

    cudaFuncSetAttribute(qkv_mm_kernel,
                         cudaFuncAttributeMaxDynamicSharedMemorySize,
                         GEMM_SMEM_BYTES);
    cudaFuncSetAttribute(oproj_mm_kernel,
                         cudaFuncAttributeMaxDynamicSharedMemorySize,
                         GEMM_SMEM_BYTES);
    cudaFuncSetAttribute(attn_mm_kernel,
                         cudaFuncAttributeMaxDynamicSharedMemorySize,
                         ATTN_SMEM_BYTES);

    prep_kernel<<<(NH * RPE_LEN + 255) / 256, 256>>>(rpe, ls);
    qkv_mm_kernel<<<dim3(ROWS / 128, DM / 128, 3), 256, GEMM_SMEM_BYTES>>>(
        query, Wq, bq, Wk, bk, Wv, bv);
    attn_mm_kernel<<<dim3(SEQ / 128, BATCH * NH), 256, ATTN_SMEM_BYTES>>>();
    oproj_mm_kernel<<<dim3(ROWS / 128, DM / 128), 256, GEMM_SMEM_BYTES>>>(
        Wp, bp, (float*)d_out);
}

// round 13
// speedup vs baseline: 1.2284x; 1.2284x over previous
#include <cuda_runtime.h>
#include <cuda_bf16.h>
#include <math.h>
#include <stdint.h>

#define BATCH 4
#define SEQ 2048
#define DM 512
#define NH 8
#define HD 64
#define ROWS (BATCH*SEQ)
#define RPE_LEN (2*SEQ-1)
#define QKV_ELEMS (BATCH*NH*SEQ*HD)

// --------- static device scratch (no allocations allowed) ------------------
__device__ __nv_bfloat16 g_xhi[ROWS*DM],   g_xlo[ROWS*DM];
__device__ __nv_bfloat16 g_whi[4*DM*DM],   g_wlo[4*DM*DM];
__device__ __nv_bfloat16 g_qhi[QKV_ELEMS], g_qlo[QKV_ELEMS];
__device__ __nv_bfloat16 g_khi[QKV_ELEMS], g_klo[QKV_ELEMS];
__device__ __nv_bfloat16 g_vthi[QKV_ELEMS], g_vtlo[QKV_ELEMS];   // (b,h,d,s)
__device__ __nv_bfloat16 g_ohi[ROWS*DM],   g_olo[ROWS*DM];
__device__ float g_sig[NH*RPE_LEN];
__device__ float g_scale[NH];

// ===========================================================================
// helpers
// ===========================================================================
__device__ __forceinline__ uint32_t smem_u32(const void* p) {
    uint32_t a;
    asm("{ .reg .u64 t; cvta.to.shared.u64 t, %1; cvt.u32.u64 %0, t; }"
        : "=r"(a) : "l"(p));
    return a;
}
__device__ __forceinline__ void mma_bf16(float d[4], const uint32_t a[4],
                                         const uint32_t b[2]) {
    asm volatile(
        "mma.sync.aligned.m16n8k16.row.col.f32.bf16.bf16.f32 "
        "{%0,%1,%2,%3}, {%4,%5,%6,%7}, {%8,%9}, {%0,%1,%2,%3};"
        : "+f"(d[0]), "+f"(d[1]), "+f"(d[2]), "+f"(d[3])
        : "r"(a[0]), "r"(a[1]), "r"(a[2]), "r"(a[3]), "r"(b[0]), "r"(b[1]));
}
__device__ __forceinline__ uint32_t pack2bf(float x0, float x1) {
    uint32_t r;
    asm("cvt.rn.bf16x2.f32 %0, %1, %2;" : "=r"(r) : "f"(x1), "f"(x0));
    return r;
}
__device__ __forceinline__ void split2(float x0, float x1,
                                       uint32_t& hp, uint32_t& lp) {
    hp = pack2bf(x0, x1);
    float h0 = __uint_as_float(hp << 16);
    float h1 = __uint_as_float(hp & 0xFFFF0000u);
    lp = pack2bf(x0 - h0, x1 - h1);
}
__device__ __forceinline__ void cp16(uint32_t dst, const void* src) {
    asm volatile("cp.async.cg.shared.global [%0], [%1], 16;"
                 :: "r"(dst), "l"(src));
}
__device__ __forceinline__ void cp4(uint32_t dst, const void* src) {
    asm volatile("cp.async.ca.shared.global [%0], [%1], 4;"
                 :: "r"(dst), "l"(src));
}
#define CP_COMMIT() asm volatile("cp.async.commit_group;" ::: "memory")
#define CP_WAIT1()  asm volatile("cp.async.wait_group 1;" ::: "memory")
#define CP_WAIT0()  asm volatile("cp.async.wait_group 0;" ::: "memory")

// ===========================================================================
// Kernel 0a: sigmoid(rpe) table + per-head scale
// ===========================================================================
__global__ void prep_kernel(const float* __restrict__ rpe,
                            const float* __restrict__ ls) {
    int i = blockIdx.x * blockDim.x + threadIdx.x;
    if (i < NH * RPE_LEN) {
        int hh = i % NH;
        int p  = i / NH;
        float x = rpe[p * NH + hh];
        g_sig[hh * RPE_LEN + p] = 1.0f / (1.0f + __expf(-x));
    }
    if (i < NH) g_scale[i] = __expf(fminf(ls[i], 4.6051701859880914f));
}

// ===========================================================================
// Kernel 0b: fp32 -> (hi, lo) bf16 split. dst_sel: 0 = X, 1 = W pool.
// ===========================================================================
__global__ void split_kernel(const float4* __restrict__ src, int dst_sel,
                             int dst_off4, int n4) {
    int i = blockIdx.x * blockDim.x + threadIdx.x;
    if (i >= n4) return;
    uint2* hi = (dst_sel == 0) ? (uint2*)g_xhi : (uint2*)g_whi;
    uint2* lo = (dst_sel == 0) ? (uint2*)g_xlo : (uint2*)g_wlo;
    float4 f = src[i];
    uint32_t h0, l0, h1, l1;
    split2(f.x, f.y, h0, l0);
    split2(f.z, f.w, h1, l1);
    hi[dst_off4 + i] = make_uint2(h0, h1);
    lo[dst_off4 + i] = make_uint2(l0, l1);
}

// ===========================================================================
// Shared pre-split 128x128 GEMM tile (K=512, chunks of 32, double-buffered).
// A/B global hi/lo bf16, row stride DM. Result -> Cs[col*CS_LD + row].
// 8 warps 2(m) x 4(n), warp tile 64x32.
// ===========================================================================
#define LDT2 40                        // chunk tile row stride (32 + 8 pad)
#define CS_LD 130
#define G_BIAS 0
#define G_T    512
#define G_BUF  40960                   // 4 tiles * 128*40*2B
#define GEMM_SMEM_BYTES (512 + 2*40960)   // 82432 (Cs 66560 aliases tiles)

__device__ __forceinline__ void gemm_tile_ps(
    const __nv_bfloat16* __restrict__ Ahg, const __nv_bfloat16* __restrict__ Alg,
    const __nv_bfloat16* __restrict__ Bhg, const __nv_bfloat16* __restrict__ Blg,
    char* sm, uint32_t smb, int tid, float* Cs) {
    const int wid = tid >> 5, lane = tid & 31;
    const int gr = lane >> 2, tg = lane & 3;
    const int wm = (wid >> 2) * 64;
    const int wn = (wid & 3) * 32;

    float acc[4][4][4] = {};

    // prologue: issue chunk 0
    {
        uint32_t base = smb + G_T;
#pragma unroll
        for (int it = 0; it < 8; ++it) {
            int id = it * 256 + tid;
            int tile = id >> 9, idx = id & 511;
            int rr = idx >> 2, gg = idx & 3;
            const __nv_bfloat16* src =
                (tile == 0 ? Ahg : tile == 1 ? Alg : tile == 2 ? Bhg : Blg) +
                (size_t)rr * DM + gg * 8;
            cp16(base + tile * 10240 + rr * 80 + gg * 16, src);
        }
        CP_COMMIT();
    }

    for (int c = 0; c < 16; ++c) {
        const int cur = c & 1;
        if (c + 1 < 16) {
            const int k0 = (c + 1) * 32;
            uint32_t base = smb + G_T + (cur ^ 1) * G_BUF;
#pragma unroll
            for (int it = 0; it < 8; ++it) {
                int id = it * 256 + tid;
                int tile = id >> 9, idx = id & 511;
                int rr = idx >> 2, gg = idx & 3;
                const __nv_bfloat16* src =
                    (tile == 0 ? Ahg : tile == 1 ? Alg : tile == 2 ? Bhg : Blg)
                    + (size_t)rr * DM + k0 + gg * 8;
                cp16(base + tile * 10240 + rr * 80 + gg * 16, src);
            }
            CP_COMMIT();
            CP_WAIT1();
        } else {
            CP_WAIT0();
        }
        __syncthreads();

        const __nv_bfloat16* Ah = (const __nv_bfloat16*)(sm + G_T + cur * G_BUF);
        const __nv_bfloat16* Al = Ah + 5120;
        const __nv_bfloat16* Bh = Ah + 10240;
        const __nv_bfloat16* Bl = Ah + 15360;

#pragma unroll
        for (int ks = 0; ks < 2; ++ks) {
            const int cc = ks * 16 + tg * 2;
            uint32_t ahi[4][4], alo[4][4];
#pragma unroll
            for (int mt = 0; mt < 4; ++mt) {
                int r0 = wm + mt * 16 + gr;
                ahi[mt][0] = *(const uint32_t*)(Ah + r0 * LDT2 + cc);
                ahi[mt][1] = *(const uint32_t*)(Ah + (r0 + 8) * LDT2 + cc);
                ahi[mt][2] = *(const uint32_t*)(Ah + r0 * LDT2 + cc + 8);
                ahi[mt][3] = *(const uint32_t*)(Ah + (r0 + 8) * LDT2 + cc + 8);
                alo[mt][0] = *(const uint32_t*)(Al + r0 * LDT2 + cc);
                alo[mt][1] = *(const uint32_t*)(Al + (r0 + 8) * LDT2 + cc);
                alo[mt][2] = *(const uint32_t*)(Al + r0 * LDT2 + cc + 8);
                alo[mt][3] = *(const uint32_t*)(Al + (r0 + 8) * LDT2 + cc + 8);
            }
#pragma unroll
            for (int nt = 0; nt < 4; ++nt) {
                int n0 = wn + nt * 8 + gr;
                uint32_t bhi[2] = {*(const uint32_t*)(Bh + n0 * LDT2 + cc),
                                   *(const uint32_t*)(Bh + n0 * LDT2 + cc + 8)};
                uint32_t blo[2] = {*(const uint32_t*)(Bl + n0 * LDT2 + cc),
                                   *(const uint32_t*)(Bl + n0 * LDT2 + cc + 8)};
#pragma unroll
                for (int mt = 0; mt < 4; ++mt) {
                    mma_bf16(acc[mt][nt], ahi[mt], bhi);
                    mma_bf16(acc[mt][nt], ahi[mt], blo);
                    mma_bf16(acc[mt][nt], alo[mt], bhi);
                }
            }
        }
        __syncthreads();
    }

    // stage C into Cs[col][row] (aliases tile buffers)
#pragma unroll
    for (int mt = 0; mt < 4; ++mt)
#pragma unroll
        for (int nt = 0; nt < 4; ++nt) {
            int r  = wm + mt * 16 + gr;
            int cl = wn + nt * 8 + tg * 2;
            Cs[cl * CS_LD + r]           = acc[mt][nt][0];
            Cs[(cl + 1) * CS_LD + r]     = acc[mt][nt][1];
            Cs[cl * CS_LD + r + 8]       = acc[mt][nt][2];
            Cs[(cl + 1) * CS_LD + r + 8] = acc[mt][nt][3];
        }
    __syncthreads();
}

// ===========================================================================
// Kernel 2: QKV projections. grid = (64, 4, 3), block 256.
// Writes Q,K row-major split-bf16; V transposed (b,h,d,s) split-bf16.
// ===========================================================================
__global__ __launch_bounds__(256) void qkv_mm_kernel() {
    extern __shared__ char sm[];
    const uint32_t smb = smem_u32(sm);
    const int tid = threadIdx.x;
    const int row0 = blockIdx.x * 128;
    const int n0   = blockIdx.y * 128;
    const int which = blockIdx.z;

    float* bsm = (float*)(sm + G_BIAS);   // bias loaded by caller wrapper
    float* Cs  = (float*)(sm + G_T);

    gemm_tile_ps(g_xhi + (size_t)row0 * DM, g_xlo + (size_t)row0 * DM,
                 g_whi + (size_t)which * DM * DM + (size_t)n0 * DM,
                 g_wlo + (size_t)which * DM * DM + (size_t)n0 * DM,
                 sm, smb, tid, Cs);

    const int b    = row0 >> 11;
    const int s_b  = row0 & (SEQ - 1);

    if (which < 2) {
        __nv_bfloat16* hiO = which ? g_khi : g_qhi;
        __nv_bfloat16* loO = which ? g_klo : g_qlo;
        const int d0base = n0 >> 3;
#pragma unroll
        for (int it = 0; it < 16; ++it) {
            int id  = it * 256 + tid;
            int g   = id & 3;
            int h   = (id >> 2) & 7;
            int row = id >> 5;
            float v[4];
#pragma unroll
            for (int u = 0; u < 4; ++u) {
                int j = h + 32 * g + 8 * u;
                v[u] = Cs[j * CS_LD + row] + bsm[j];
            }
            int s  = s_b + row;
            int d0 = d0base + 4 * g;
            size_t off = ((size_t)((b * NH + h) * SEQ + s)) * HD + d0;
            uint32_t h0, l0, h1, l1;
            split2(v[0], v[1], h0, l0);
            split2(v[2], v[3], h1, l1);
            *(uint2*)(hiO + off) = make_uint2(h0, h1);
            *(uint2*)(loO + off) = make_uint2(l0, l1);
        }
    } else {
        // V transposed: vt[(b*NH+h)*HD + d][s]
#pragma unroll
        for (int it = 0; it < 16; ++it) {
            int id   = it * 256 + tid;
            int rblk = id & 31;           // lane within warp
            int j    = id >> 5;           // column 0..127 (warp-uniform-ish)
            int wr   = n0 + j;
            int h    = wr & 7;
            int d    = wr >> 3;
            float bj = bsm[j];
            float2 c0 = *(float2*)&Cs[j * CS_LD + rblk * 4];
            float2 c1 = *(float2*)&Cs[j * CS_LD + rblk * 4 + 2];
            float v0 = c0.x + bj, v1 = c0.y + bj;
            float v2 = c1.x + bj, v3 = c1.y + bj;
            size_t off = ((size_t)((b * NH + h) * HD + d)) * SEQ + s_b + rblk * 4;
            uint32_t h0, l0, h1, l1;
            split2(v0, v1, h0, l0);
            split2(v2, v3, h1, l1);
            *(uint2*)(g_vthi + off) = make_uint2(h0, h1);
            *(uint2*)(g_vtlo + off) = make_uint2(l0, l1);
        }
    }
}

// wrapper kernels can't easily pass bias; load it at kernel start instead:
__global__ __launch_bounds__(256) void qkv_mm_kernel_b(
    const float* __restrict__ bq, const float* __restrict__ bk,
    const float* __restrict__ bv);

// ===========================================================================
// Kernel 4: output projection. grid = (64, 4), block 256. fp32 out.
// ===========================================================================
__global__ __launch_bounds__(256) void oproj_mm_kernel(
    const float* __restrict__ bp, float* __restrict__ out) {
    extern __shared__ char sm[];
    const uint32_t smb = smem_u32(sm);
    const int tid = threadIdx.x;
    const int row0 = blockIdx.x * 128;
    const int n0   = blockIdx.y * 128;

    float* bsm = (float*)(sm + G_BIAS);
    if (tid < 128) bsm[tid] = bp[n0 + tid];
    float* Cs = (float*)(sm + G_T);

    gemm_tile_ps(g_ohi + (size_t)row0 * DM, g_olo + (size_t)row0 * DM,
                 g_whi + (size_t)3 * DM * DM + (size_t)n0 * DM,
                 g_wlo + (size_t)3 * DM * DM + (size_t)n0 * DM,
                 sm, smb, tid, Cs);

#pragma unroll
    for (int it = 0; it < 16; ++it) {
        int id  = it * 256 + tid;
        int q4  = id & 31;
        int row = id >> 5;
        float v[4];
#pragma unroll
        for (int u = 0; u < 4; ++u) {
            int j = 4 * q4 + u;
            v[u] = Cs[j * CS_LD + row] + bsm[j];
        }
        *(float4*)(out + (size_t)(row0 + row) * DM + n0 + 4 * q4) =
            make_float4(v[0], v[1], v[2], v[3]);
    }
}

// ===========================================================================
// Kernel 3: flash attention via mma.sync, pre-split inputs, cp.async
// double-buffered tiles. grid = (16, 32), block 256.
// smem: sg 2x192 f32 @0; tiles @1536, 2 buffers of
//   Khi(9216) Klo(9216) Vthi(9216) Vtlo(9216) — 36864 each.
// ===========================================================================
#define ALDT 72
#define ATT_SG 0
#define ATT_T  1536
#define ATT_BUF 36864
#define ATTN_SMEM_BYTES (1536 + 2*36864)

__global__ __launch_bounds__(256) void attn_mm_kernel() {
    extern __shared__ char sm[];
    const uint32_t smb = smem_u32(sm);
    const int tid = threadIdx.x, wid = tid >> 5, lane = tid & 31;
    const int gr = lane >> 2, tg = lane & 3;
    const int bh = blockIdx.y, b = bh >> 3, h = bh & 7;
    const int q0 = blockIdx.x * 128;
    const __nv_bfloat16* Qh = g_qhi + (size_t)bh * SEQ * HD;
    const __nv_bfloat16* Ql = g_qlo + (size_t)bh * SEQ * HD;
    const __nv_bfloat16* Kh = g_khi + (size_t)bh * SEQ * HD;
    const __nv_bfloat16* Kl = g_klo + (size_t)bh * SEQ * HD;
    const __nv_bfloat16* Vh = g_vthi + (size_t)bh * HD * SEQ;
    const __nv_bfloat16* Vl = g_vtlo + (size_t)bh * HD * SEQ;
    const float cscale = g_scale[h] * 0.04419417382415922f;  // 1/sqrt(512)

    // ---- stage Q tile, lift fragments (region reused by buf0 afterwards)
    uint32_t qhi[4][4], qlo[4][4];
    {
        __nv_bfloat16* Qshi = (__nv_bfloat16*)(sm + ATT_T);
        __nv_bfloat16* Qslo = (__nv_bfloat16*)(sm + ATT_T + 18432);
#pragma unroll
        for (int it = 0; it < 8; ++it) {
            int id = it * 256 + tid;            // 0..2047
            int arr = id >> 10, rr = (id >> 3) & 127, gg = id & 7;
            const __nv_bfloat16* src =
                (arr ? Ql : Qh) + (size_t)(q0 + rr) * HD + gg * 8;
            *(uint4*)((arr ? Qslo : Qshi) + rr * ALDT + gg * 8) =
                *(const uint4*)src;
        }
        __syncthreads();
        int r0 = wid * 16 + gr;
#pragma unroll
        for (int ks = 0; ks < 4; ++ks) {
            int cc = ks * 16 + tg * 2;
            qhi[ks][0] = *(uint32_t*)(Qshi + r0 * ALDT + cc);
            qhi[ks][1] = *(uint32_t*)(Qshi + (r0 + 8) * ALDT + cc);
            qhi[ks][2] = *(uint32_t*)(Qshi + r0 * ALDT + cc + 8);
            qhi[ks][3] = *(uint32_t*)(Qshi + (r0 + 8) * ALDT + cc + 8);
            qlo[ks][0] = *(uint32_t*)(Qslo + r0 * ALDT + cc);
            qlo[ks][1] = *(uint32_t*)(Qslo + (r0 + 8) * ALDT + cc);
            qlo[ks][2] = *(uint32_t*)(Qslo + r0 * ALDT + cc + 8);
            qlo[ks][3] = *(uint32_t*)(Qslo + (r0 + 8) * ALDT + cc + 8);
        }
        __syncthreads();
    }

    float m0r = -1e30f, m1r = -1e30f, l0r = 0.0f, l1r = 0.0f;
    float Oa[8][4] = {};
    const int qi0 = wid * 16 + gr;

    // prologue: issue tile 0 into buf 0
    {
        uint32_t base = smb + ATT_T;
#pragma unroll
        for (int it = 0; it < 8; ++it) {
            int id = it * 256 + tid;
            int tile = id >> 9, idx = id & 511;
            int rr = idx >> 3, gg = idx & 7;
            const __nv_bfloat16* src;
            if (tile == 0)      src = Kh + (size_t)rr * HD + gg * 8;
            else if (tile == 1) src = Kl + (size_t)rr * HD + gg * 8;
            else if (tile == 2) src = Vh + (size_t)rr * SEQ + gg * 8;
            else                src = Vl + (size_t)rr * SEQ + gg * 8;
            cp16(base + tile * 9216 + rr * 144 + gg * 16, src);
        }
        if (tid < 192)
            cp4(smb + ATT_SG + tid * 4,
                &g_sig[h * RPE_LEN + q0 + 1984 + tid]);
        CP_COMMIT();
    }

    for (int kt = 0; kt < 32; ++kt) {
        const int cur = kt & 1;
        if (kt + 1 < 32) {
            const int k0n = (kt + 1) * 64;
            uint32_t base = smb + ATT_T + (cur ^ 1) * ATT_BUF;
#pragma unroll
            for (int it = 0; it < 8; ++it) {
                int id = it * 256 + tid;
                int tile = id >> 9, idx = id & 511;
                int rr = idx >> 3, gg = idx & 7;
                const __nv_bfloat16* src;
                if (tile == 0)      src = Kh + (size_t)(k0n + rr) * HD + gg * 8;
                else if (tile == 1) src = Kl + (size_t)(k0n + rr) * HD + gg * 8;
                else if (tile == 2) src = Vh + (size_t)rr * SEQ + k0n + gg * 8;
                else                src = Vl + (size_t)rr * SEQ + k0n + gg * 8;
                cp16(base + tile * 9216 + rr * 144 + gg * 16, src);
            }
            if (tid < 192)
                cp4(smb + ATT_SG + (cur ^ 1) * 768 + tid * 4,
                    &g_sig[h * RPE_LEN + q0 - k0n + 1984 + tid]);
            CP_COMMIT();
            CP_WAIT1();
        } else {
            CP_WAIT0();
        }
        __syncthreads();

        const __nv_bfloat16* Khi_s =
            (const __nv_bfloat16*)(sm + ATT_T + cur * ATT_BUF);
        const __nv_bfloat16* Klo_s  = Khi_s + 4608;
        const __nv_bfloat16* Vthi_s = Khi_s + 9216;
        const __nv_bfloat16* Vtlo_s = Khi_s + 13824;
        const float* sgp = (const float*)(sm + ATT_SG + cur * 768);

        // ---- S = Q K^T
        float p[8][4];
#pragma unroll
        for (int nt = 0; nt < 8; ++nt) {
            p[nt][0] = p[nt][1] = p[nt][2] = p[nt][3] = 0.0f;
            int n0 = nt * 8 + gr;
#pragma unroll
            for (int ks = 0; ks < 4; ++ks) {
                int cc = ks * 16 + tg * 2;
                uint32_t bhi[2] = {*(uint32_t*)(Khi_s + n0 * ALDT + cc),
                                   *(uint32_t*)(Khi_s + n0 * ALDT + cc + 8)};
                uint32_t blo[2] = {*(uint32_t*)(Klo_s + n0 * ALDT + cc),
                                   *(uint32_t*)(Klo_s + n0 * ALDT + cc + 8)};
                mma_bf16(p[nt], qhi[ks], bhi);
                mma_bf16(p[nt], qhi[ks], blo);
                mma_bf16(p[nt], qlo[ks], bhi);
            }
        }

        // ---- scale + RPE bias + online softmax
        float rmax0 = -1e30f, rmax1 = -1e30f;
#pragma unroll
        for (int nt = 0; nt < 8; ++nt) {
            int kj = nt * 8 + tg * 2;
            p[nt][0] = p[nt][0] * cscale + sgp[qi0 - kj + 63];
            p[nt][1] = p[nt][1] * cscale + sgp[qi0 - kj + 62];
            p[nt][2] = p[nt][2] * cscale + sgp[qi0 - kj + 71];
            p[nt][3] = p[nt][3] * cscale + sgp[qi0 - kj + 70];
            rmax0 = fmaxf(rmax0, fmaxf(p[nt][0], p[nt][1]));
            rmax1 = fmaxf(rmax1, fmaxf(p[nt][2], p[nt][3]));
        }
#pragma unroll
        for (int off = 1; off <= 2; off <<= 1) {
            rmax0 = fmaxf(rmax0, __shfl_xor_sync(0xffffffffu, rmax0, off));
            rmax1 = fmaxf(rmax1, __shfl_xor_sync(0xffffffffu, rmax1, off));
        }
        float mn0 = fmaxf(m0r, rmax0), mn1 = fmaxf(m1r, rmax1);
        float al0 = __expf(m0r - mn0), al1 = __expf(m1r - mn1);
        float rs0 = 0.0f, rs1 = 0.0f;
#pragma unroll
        for (int nt = 0; nt < 8; ++nt) {
            p[nt][0] = __expf(p[nt][0] - mn0);
            p[nt][1] = __expf(p[nt][1] - mn0);
            p[nt][2] = __expf(p[nt][2] - mn1);
            p[nt][3] = __expf(p[nt][3] - mn1);
            rs0 += p[nt][0] + p[nt][1];
            rs1 += p[nt][2] + p[nt][3];
        }
#pragma unroll
        for (int off = 1; off <= 2; off <<= 1) {
            rs0 += __shfl_xor_sync(0xffffffffu, rs0, off);
            rs1 += __shfl_xor_sync(0xffffffffu, rs1, off);
        }
        l0r = l0r * al0 + rs0;
        l1r = l1r * al1 + rs1;
        m0r = mn0;
        m1r = mn1;
#pragma unroll
        for (int nt = 0; nt < 8; ++nt) {
            Oa[nt][0] *= al0; Oa[nt][1] *= al0;
            Oa[nt][2] *= al1; Oa[nt][3] *= al1;
        }

        // ---- pack P into split A-fragments (register-only)
        uint32_t phi[4][4], plo[4][4];
#pragma unroll
        for (int ks2 = 0; ks2 < 4; ++ks2) {
            int ntA = 2 * ks2, ntB = 2 * ks2 + 1;
            split2(p[ntA][0], p[ntA][1], phi[ks2][0], plo[ks2][0]);
            split2(p[ntA][2], p[ntA][3], phi[ks2][1], plo[ks2][1]);
            split2(p[ntB][0], p[ntB][1], phi[ks2][2], plo[ks2][2]);
            split2(p[ntB][2], p[ntB][3], phi[ks2][3], plo[ks2][3]);
        }

        // ---- O += P V
#pragma unroll
        for (int nt = 0; nt < 8; ++nt) {
            int n0 = nt * 8 + gr;
#pragma unroll
            for (int ks2 = 0; ks2 < 4; ++ks2) {
                int cc = ks2 * 16 + tg * 2;
                uint32_t vhi[2] = {*(uint32_t*)(Vthi_s + n0 * ALDT + cc),
                                   *(uint32_t*)(Vthi_s + n0 * ALDT + cc + 8)};
                uint32_t vlo[2] = {*(uint32_t*)(Vtlo_s + n0 * ALDT + cc),
                                   *(uint32_t*)(Vtlo_s + n0 * ALDT + cc + 8)};
                mma_bf16(Oa[nt], phi[ks2], vhi);
                mma_bf16(Oa[nt], phi[ks2], vlo);
                mma_bf16(Oa[nt], plo[ks2], vhi);
            }
        }
        __syncthreads();
    }

    // ---- normalize, write split-bf16 concat-head output
    float inv0 = 1.0f / l0r, inv1 = 1.0f / l1r;
    int qrow = q0 + qi0;
#pragma unroll
    for (int nt = 0; nt < 8; ++nt) {
        int col = h * HD + nt * 8 + tg * 2;
        size_t off0 = (size_t)(b * SEQ + qrow) * DM + col;
        size_t off1 = (size_t)(b * SEQ + qrow + 8) * DM + col;
        uint32_t hp, lp;
        split2(Oa[nt][0] * inv0, Oa[nt][1] * inv0, hp, lp);
        *(uint32_t*)(g_ohi + off0) = hp;
        *(uint32_t*)(g_olo + off0) = lp;
        split2(Oa[nt][2] * inv1, Oa[nt][3] * inv1, hp, lp);
        *(uint32_t*)(g_ohi + off1) = hp;
        *(uint32_t*)(g_olo + off1) = lp;
    }
}

// ===========================================================================
// qkv with bias parameters (real definition)
// ===========================================================================
__global__ __launch_bounds__(256) void qkv_mm_kernel_b(
    const float* __restrict__ bq, const float* __restrict__ bk,
    const float* __restrict__ bv) {
    extern __shared__ char sm[];
    const int tid = threadIdx.x;
    const int n0  = blockIdx.y * 128;
    const int which = blockIdx.z;
    const float* bias = (which == 0) ? bq : (which == 1) ? bk : bv;
    float* bsm = (float*)(sm + G_BIAS);
    if (tid < 128) bsm[tid] = bias[n0 + tid];
    qkv_mm_kernel_body:;
    // delegate to shared body via inline (duplicated logic below)
    {
        const uint32_t smb = smem_u32(sm);
        const int row0 = blockIdx.x * 128;
        float* Cs = (float*)(sm + G_T);
        gemm_tile_ps(g_xhi + (size_t)row0 * DM, g_xlo + (size_t)row0 * DM,
                     g_whi + (size_t)which * DM * DM + (size_t)n0 * DM,
                     g_wlo + (size_t)which * DM * DM + (size_t)n0 * DM,
                     sm, smb, tid, Cs);
        const int b   = row0 >> 11;
        const int s_b = row0 & (SEQ - 1);
        if (which < 2) {
            __nv_bfloat16* hiO = which ? g_khi : g_qhi;
            __nv_bfloat16* loO = which ? g_klo : g_qlo;
            const int d0base = n0 >> 3;
#pragma unroll
            for (int it = 0; it < 16; ++it) {
                int id  = it * 256 + tid;
                int g   = id & 3;
                int h   = (id >> 2) & 7;
                int row = id >> 5;
                float v[4];
#pragma unroll
                for (int u = 0; u < 4; ++u) {
                    int j = h + 32 * g + 8 * u;
                    v[u] = Cs[j * CS_LD + row] + bsm[j];
                }
                int s  = s_b + row;
                int d0 = d0base + 4 * g;
                size_t off = ((size_t)((b * NH + h) * SEQ + s)) * HD + d0;
                uint32_t h0, l0, h1, l1;
                split2(v[0], v[1], h0, l0);
                split2(v[2], v[3], h1, l1);
                *(uint2*)(hiO + off) = make_uint2(h0, h1);
                *(uint2*)(loO + off) = make_uint2(l0, l1);
            }
        } else {
#pragma unroll
            for (int it = 0; it < 16; ++it) {
                int id   = it * 256 + tid;
                int rblk = id & 31;
                int j    = id >> 5;
                int wr   = n0 + j;
                int h    = wr & 7;
                int d    = wr >> 3;
                float bj = bsm[j];
                float2 c0 = *(float2*)&Cs[j * CS_LD + rblk * 4];
                float2 c1 = *(float2*)&Cs[j * CS_LD + rblk * 4 + 2];
                float v0 = c0.x + bj, v1 = c0.y + bj;
                float v2 = c1.x + bj, v3 = c1.y + bj;
                size_t off =
                    ((size_t)((b * NH + h) * HD + d)) * SEQ + s_b + rblk * 4;
                uint32_t h0, l0, h1, l1;
                split2(v0, v1, h0, l0);
                split2(v2, v3, h1, l1);
                *(uint2*)(g_vthi + off) = make_uint2(h0, h1);
                *(uint2*)(g_vtlo + off) = make_uint2(l0, l1);
            }
        }
    }
}

// ---------------------------------------------------------------------------
extern "C" void kernel_launch(void* const* d_in, const int* in_sizes, int n_in,
                              void* d_out, int out_size) {
    (void)in_sizes; (void)n_in; (void)out_size;
    const float* query = (const float*)d_in[0];
    const float* Wq = (const float*)d_in[1];
    const float* bq = (const float*)d_in[2];
    const float* Wk = (const float*)d_in[3];
    const float* bk = (const float*)d_in[4];
    const float* Wv = (const float*)d_in[5];
    const float* bv = (const float*)d_in[6];
    const float* Wp = (const float*)d_in[7];
    const float* bp = (const float*)d_in[8];
    const float* ls = (const float*)d_in[9];
    const float* rpe = (const float*)d_in[10];

    cudaFuncSetAttribute(qkv_mm_kernel_b,
                         cudaFuncAttributeMaxDynamicSharedMemorySize,
                         GEMM_SMEM_BYTES);
    cudaFuncSetAttribute(oproj_mm_kernel,
                         cudaFuncAttributeMaxDynamicSharedMemorySize,
                         GEMM_SMEM_BYTES);
    cudaFuncSetAttribute(attn_mm_kernel,
                         cudaFuncAttributeMaxDynamicSharedMemorySize,
                         ATTN_SMEM_BYTES);

    prep_kernel<<<(NH * RPE_LEN + 255) / 256, 256>>>(rpe, ls);
    split_kernel<<<4096, 256>>>((const float4*)query, 0, 0, ROWS * DM / 4);
    split_kernel<<<256, 256>>>((const float4*)Wq, 1, 0 * DM * DM / 4, DM * DM / 4);
    split_kernel<<<256, 256>>>((const float4*)Wk, 1, 1 * DM * DM / 4, DM * DM / 4);
    split_kernel<<<256, 256>>>((const float4*)Wv, 1, 2 * DM * DM / 4, DM * DM / 4);
    split_kernel<<<256, 256>>>((const float4*)Wp, 1, 3 * DM * DM / 4, DM * DM / 4);

    qkv_mm_kernel_b<<<dim3(ROWS / 128, DM / 128, 3), 256, GEMM_SMEM_BYTES>>>(
        bq, bk, bv);
    attn_mm_kernel<<<dim3(SEQ / 128, BATCH * NH), 256, ATTN_SMEM_BYTES>>>();
    oproj_mm_kernel<<<dim3(ROWS / 128, DM / 128), 256, GEMM_SMEM_BYTES>>>(
        bp, (float*)d_out);
}

// round 14
// speedup vs baseline: 1.3186x; 1.0735x over previous
#include <cuda_runtime.h>
#include <cuda_bf16.h>
#include <math.h>
#include <stdint.h>

#define BATCH 4
#define SEQ 2048
#define DM 512
#define NH 8
#define HD 64
#define ROWS (BATCH*SEQ)
#define RPE_LEN (2*SEQ-1)
#define QKV_ELEMS (BATCH*NH*SEQ*HD)

// --------- static device scratch (no allocations allowed) ------------------
__device__ __nv_bfloat16 g_xhi[ROWS*DM],   g_xlo[ROWS*DM];
__device__ __nv_bfloat16 g_whi[4*DM*DM],   g_wlo[4*DM*DM];
__device__ __nv_bfloat16 g_qhi[QKV_ELEMS], g_qlo[QKV_ELEMS];
__device__ __nv_bfloat16 g_khi[QKV_ELEMS], g_klo[QKV_ELEMS];
__device__ __nv_bfloat16 g_vthi[QKV_ELEMS], g_vtlo[QKV_ELEMS];   // (b,h,d,s)
__device__ __nv_bfloat16 g_ohi[ROWS*DM],   g_olo[ROWS*DM];
__device__ float g_sig[NH*RPE_LEN];
__device__ float g_scale[NH];

// ===========================================================================
// helpers
// ===========================================================================
__device__ __forceinline__ uint32_t smem_u32(const void* p) {
    uint32_t a;
    asm("{ .reg .u64 t; cvta.to.shared.u64 t, %1; cvt.u32.u64 %0, t; }"
        : "=r"(a) : "l"(p));
    return a;
}
__device__ __forceinline__ void mma_bf16(float d[4], const uint32_t a[4],
                                         const uint32_t b[2]) {
    asm volatile(
        "mma.sync.aligned.m16n8k16.row.col.f32.bf16.bf16.f32 "
        "{%0,%1,%2,%3}, {%4,%5,%6,%7}, {%8,%9}, {%0,%1,%2,%3};"
        : "+f"(d[0]), "+f"(d[1]), "+f"(d[2]), "+f"(d[3])
        : "r"(a[0]), "r"(a[1]), "r"(a[2]), "r"(a[3]), "r"(b[0]), "r"(b[1]));
}
__device__ __forceinline__ void ldm_x4(uint32_t r[4], uint32_t a) {
    asm volatile(
        "ldmatrix.sync.aligned.m8n8.x4.shared.b16 {%0,%1,%2,%3}, [%4];"
        : "=r"(r[0]), "=r"(r[1]), "=r"(r[2]), "=r"(r[3]) : "r"(a));
}
__device__ __forceinline__ uint32_t pack2bf(float x0, float x1) {
    uint32_t r;
    asm("cvt.rn.bf16x2.f32 %0, %1, %2;" : "=r"(r) : "f"(x1), "f"(x0));
    return r;
}
__device__ __forceinline__ void split2(float x0, float x1,
                                       uint32_t& hp, uint32_t& lp) {
    hp = pack2bf(x0, x1);
    float h0 = __uint_as_float(hp << 16);
    float h1 = __uint_as_float(hp & 0xFFFF0000u);
    lp = pack2bf(x0 - h0, x1 - h1);
}
__device__ __forceinline__ void cp16(uint32_t dst, const void* src) {
    asm volatile("cp.async.cg.shared.global [%0], [%1], 16;"
                 :: "r"(dst), "l"(src));
}
__device__ __forceinline__ void cp4(uint32_t dst, const void* src) {
    asm volatile("cp.async.ca.shared.global [%0], [%1], 4;"
                 :: "r"(dst), "l"(src));
}
#define CP_COMMIT() asm volatile("cp.async.commit_group;" ::: "memory")
#define CP_WAIT1()  asm volatile("cp.async.wait_group 1;" ::: "memory")
#define CP_WAIT0()  asm volatile("cp.async.wait_group 0;" ::: "memory")

// ===========================================================================
// Kernel 0a: sigmoid(rpe) table + per-head scale
// ===========================================================================
__global__ void prep_kernel(const float* __restrict__ rpe,
                            const float* __restrict__ ls) {
    int i = blockIdx.x * blockDim.x + threadIdx.x;
    if (i < NH * RPE_LEN) {
        int hh = i % NH;
        int p  = i / NH;
        float x = rpe[p * NH + hh];
        g_sig[hh * RPE_LEN + p] = 1.0f / (1.0f + __expf(-x));
    }
    if (i < NH) g_scale[i] = __expf(fminf(ls[i], 4.6051701859880914f));
}

// ===========================================================================
// Kernel 0b: fp32 -> (hi, lo) bf16 split. dst_sel: 0 = X, 1 = W pool.
// ===========================================================================
__global__ void split_kernel(const float4* __restrict__ src, int dst_sel,
                             int dst_off4, int n4) {
    int i = blockIdx.x * blockDim.x + threadIdx.x;
    if (i >= n4) return;
    uint2* hi = (dst_sel == 0) ? (uint2*)g_xhi : (uint2*)g_whi;
    uint2* lo = (dst_sel == 0) ? (uint2*)g_xlo : (uint2*)g_wlo;
    float4 f = src[i];
    uint32_t h0, l0, h1, l1;
    split2(f.x, f.y, h0, l0);
    split2(f.z, f.w, h1, l1);
    hi[dst_off4 + i] = make_uint2(h0, h1);
    lo[dst_off4 + i] = make_uint2(l0, l1);
}

// ===========================================================================
// Pre-split 128x128 GEMM tile, K=512 in 8 chunks of 64, double-buffered,
// ldmatrix fragment loads. 8 warps 2(m) x 4(n), warp tile 64x32.
// buffer layout (bytes): Ahi 0, Alo 18432, Bhi 36864, Blo 55296 (LDTG=72)
// ===========================================================================
#define LDTG 72
#define CS_LD 130
#define G_BIAS 0
#define G_T    512
#define G_BUF  73728
#define GEMM_SMEM_BYTES (512 + 2*73728)   // 147968

__device__ __forceinline__ void gemm_tile_ps(
    const __nv_bfloat16* __restrict__ Ahg, const __nv_bfloat16* __restrict__ Alg,
    const __nv_bfloat16* __restrict__ Bhg, const __nv_bfloat16* __restrict__ Blg,
    uint32_t smb, int tid, float* Cs) {
    const int wid = tid >> 5, lane = tid & 31;
    const int gr = lane >> 2, tg = lane & 3;
    const int wm = (wid >> 2) * 64;
    const int wn = (wid & 3) * 32;
    // ldmatrix lane mappings
    const int arow = lane & 15, acol = (lane >> 4) * 8;          // A x4
    const int b_roff = (((lane >> 3) >> 1) & 1) * 8 + (lane & 7);  // B x4
    const int b_koff = ((lane >> 3) & 1) * 8;

    float acc[4][4][4] = {};

    // prologue: chunk 0
    {
        uint32_t base = smb + G_T;
#pragma unroll
        for (int it = 0; it < 16; ++it) {
            int id = it * 256 + tid;
            int tile = id >> 10, idx = id & 1023;
            int rr = idx >> 3, gg = idx & 7;
            const __nv_bfloat16* src =
                (tile == 0 ? Ahg : tile == 1 ? Alg : tile == 2 ? Bhg : Blg) +
                (size_t)rr * DM + gg * 8;
            cp16(base + tile * 18432 + rr * 144 + gg * 16, src);
        }
        CP_COMMIT();
    }

    for (int c = 0; c < 8; ++c) {
        const int cur = c & 1;
        if (c + 1 < 8) {
            const int k0 = (c + 1) * 64;
            uint32_t base = smb + G_T + (cur ^ 1) * G_BUF;
#pragma unroll
            for (int it = 0; it < 16; ++it) {
                int id = it * 256 + tid;
                int tile = id >> 10, idx = id & 1023;
                int rr = idx >> 3, gg = idx & 7;
                const __nv_bfloat16* src =
                    (tile == 0 ? Ahg : tile == 1 ? Alg : tile == 2 ? Bhg : Blg)
                    + (size_t)rr * DM + k0 + gg * 8;
                cp16(base + tile * 18432 + rr * 144 + gg * 16, src);
            }
            CP_COMMIT();
            CP_WAIT1();
        } else {
            CP_WAIT0();
        }
        __syncthreads();

        const uint32_t base = smb + G_T + cur * G_BUF;
#pragma unroll
        for (int ks = 0; ks < 4; ++ks) {
            const int cc = ks * 16;
            uint32_t ahi[4][4], alo[4][4];
#pragma unroll
            for (int mt = 0; mt < 4; ++mt) {
                uint32_t aadr =
                    base + ((wm + mt * 16 + arow) * LDTG + cc + acol) * 2;
                ldm_x4(ahi[mt], aadr);
                ldm_x4(alo[mt], aadr + 18432);
            }
#pragma unroll
            for (int pp = 0; pp < 2; ++pp) {
                uint32_t bh4[4], bl4[4];
                uint32_t badr = base + 36864 +
                    ((wn + pp * 16 + b_roff) * LDTG + cc + b_koff) * 2;
                ldm_x4(bh4, badr);
                ldm_x4(bl4, badr + 18432);
#pragma unroll
                for (int q = 0; q < 2; ++q) {
                    int nt = 2 * pp + q;
                    uint32_t bh2[2] = {bh4[2 * q], bh4[2 * q + 1]};
                    uint32_t bl2[2] = {bl4[2 * q], bl4[2 * q + 1]};
#pragma unroll
                    for (int mt = 0; mt < 4; ++mt) {
                        mma_bf16(acc[mt][nt], ahi[mt], bh2);
                        mma_bf16(acc[mt][nt], ahi[mt], bl2);
                        mma_bf16(acc[mt][nt], alo[mt], bh2);
                    }
                }
            }
        }
        __syncthreads();
    }

    // stage C into Cs[col][row] (aliases tile buffers)
#pragma unroll
    for (int mt = 0; mt < 4; ++mt)
#pragma unroll
        for (int nt = 0; nt < 4; ++nt) {
            int r  = wm + mt * 16 + gr;
            int cl = wn + nt * 8 + tg * 2;
            Cs[cl * CS_LD + r]           = acc[mt][nt][0];
            Cs[(cl + 1) * CS_LD + r]     = acc[mt][nt][1];
            Cs[cl * CS_LD + r + 8]       = acc[mt][nt][2];
            Cs[(cl + 1) * CS_LD + r + 8] = acc[mt][nt][3];
        }
    __syncthreads();
}

// ===========================================================================
// Kernel 2: QKV projections. grid = (64, 4, 3), block 256.
// Writes Q,K row-major split-bf16; V transposed (b,h,d,s) split-bf16.
// ===========================================================================
__global__ __launch_bounds__(256) void qkv_mm_kernel_b(
    const float* __restrict__ bq, const float* __restrict__ bk,
    const float* __restrict__ bv) {
    extern __shared__ char sm[];
    const uint32_t smb = smem_u32(sm);
    const int tid = threadIdx.x;
    const int row0 = blockIdx.x * 128;
    const int n0   = blockIdx.y * 128;
    const int which = blockIdx.z;
    const float* bias = (which == 0) ? bq : (which == 1) ? bk : bv;
    float* bsm = (float*)(sm + G_BIAS);
    if (tid < 128) bsm[tid] = bias[n0 + tid];

    float* Cs = (float*)(sm + G_T);
    gemm_tile_ps(g_xhi + (size_t)row0 * DM, g_xlo + (size_t)row0 * DM,
                 g_whi + (size_t)which * DM * DM + (size_t)n0 * DM,
                 g_wlo + (size_t)which * DM * DM + (size_t)n0 * DM,
                 smb, tid, Cs);

    const int b   = row0 >> 11;
    const int s_b = row0 & (SEQ - 1);
    if (which < 2) {
        __nv_bfloat16* hiO = which ? g_khi : g_qhi;
        __nv_bfloat16* loO = which ? g_klo : g_qlo;
        const int d0base = n0 >> 3;
#pragma unroll
        for (int it = 0; it < 16; ++it) {
            int id  = it * 256 + tid;
            int g   = id & 3;
            int h   = (id >> 2) & 7;
            int row = id >> 5;
            float v[4];
#pragma unroll
            for (int u = 0; u < 4; ++u) {
                int j = h + 32 * g + 8 * u;
                v[u] = Cs[j * CS_LD + row] + bsm[j];
            }
            int s  = s_b + row;
            int d0 = d0base + 4 * g;
            size_t off = ((size_t)((b * NH + h) * SEQ + s)) * HD + d0;
            uint32_t h0, l0, h1, l1;
            split2(v[0], v[1], h0, l0);
            split2(v[2], v[3], h1, l1);
            *(uint2*)(hiO + off) = make_uint2(h0, h1);
            *(uint2*)(loO + off) = make_uint2(l0, l1);
        }
    } else {
        // V transposed: vt[(b*NH+h)*HD + d][s]
#pragma unroll
        for (int it = 0; it < 16; ++it) {
            int id   = it * 256 + tid;
            int rblk = id & 31;
            int j    = id >> 5;
            int wr   = n0 + j;
            int h    = wr & 7;
            int d    = wr >> 3;
            float bj = bsm[j];
            float2 c0 = *(float2*)&Cs[j * CS_LD + rblk * 4];
            float2 c1 = *(float2*)&Cs[j * CS_LD + rblk * 4 + 2];
            float v0 = c0.x + bj, v1 = c0.y + bj;
            float v2 = c1.x + bj, v3 = c1.y + bj;
            size_t off =
                ((size_t)((b * NH + h) * HD + d)) * SEQ + s_b + rblk * 4;
            uint32_t h0, l0, h1, l1;
            split2(v0, v1, h0, l0);
            split2(v2, v3, h1, l1);
            *(uint2*)(g_vthi + off) = make_uint2(h0, h1);
            *(uint2*)(g_vtlo + off) = make_uint2(l0, l1);
        }
    }
}

// ===========================================================================
// Kernel 4: output projection. grid = (64, 4), block 256. fp32 out.
// ===========================================================================
__global__ __launch_bounds__(256) void oproj_mm_kernel(
    const float* __restrict__ bp, float* __restrict__ out) {
    extern __shared__ char sm[];
    const uint32_t smb = smem_u32(sm);
    const int tid = threadIdx.x;
    const int row0 = blockIdx.x * 128;
    const int n0   = blockIdx.y * 128;

    float* bsm = (float*)(sm + G_BIAS);
    if (tid < 128) bsm[tid] = bp[n0 + tid];
    float* Cs = (float*)(sm + G_T);

    gemm_tile_ps(g_ohi + (size_t)row0 * DM, g_olo + (size_t)row0 * DM,
                 g_whi + (size_t)3 * DM * DM + (size_t)n0 * DM,
                 g_wlo + (size_t)3 * DM * DM + (size_t)n0 * DM,
                 smb, tid, Cs);

#pragma unroll
    for (int it = 0; it < 16; ++it) {
        int id  = it * 256 + tid;
        int q4  = id & 31;
        int row = id >> 5;
        float v[4];
#pragma unroll
        for (int u = 0; u < 4; ++u) {
            int j = 4 * q4 + u;
            v[u] = Cs[j * CS_LD + row] + bsm[j];
        }
        *(float4*)(out + (size_t)(row0 + row) * DM + n0 + 4 * q4) =
            make_float4(v[0], v[1], v[2], v[3]);
    }
}

// ===========================================================================
// Kernel 3: flash attention, pre-split inputs, cp.async double-buffered,
// ldmatrix K/V fragment loads. grid = (16, 32), block 256.
// smem: sg 2x192 f32 @0; tiles @1536, 2 buffers of
//   Khi(9216) Klo(9216) Vthi(9216) Vtlo(9216) bytes — 36864 each.
// ===========================================================================
#define ALDT 72
#define ATT_SG 0
#define ATT_T  1536
#define ATT_BUF 36864
#define ATTN_SMEM_BYTES (1536 + 2*36864)

__global__ __launch_bounds__(256) void attn_mm_kernel() {
    extern __shared__ char sm[];
    const uint32_t smb = smem_u32(sm);
    const int tid = threadIdx.x, wid = tid >> 5, lane = tid & 31;
    const int gr = lane >> 2, tg = lane & 3;
    const int b_roff = (((lane >> 3) >> 1) & 1) * 8 + (lane & 7);
    const int b_koff = ((lane >> 3) & 1) * 8;
    const int bh = blockIdx.y, b = bh >> 3, h = bh & 7;
    const int q0 = blockIdx.x * 128;
    const __nv_bfloat16* Qh = g_qhi + (size_t)bh * SEQ * HD;
    const __nv_bfloat16* Ql = g_qlo + (size_t)bh * SEQ * HD;
    const __nv_bfloat16* Kh = g_khi + (size_t)bh * SEQ * HD;
    const __nv_bfloat16* Kl = g_klo + (size_t)bh * SEQ * HD;
    const __nv_bfloat16* Vh = g_vthi + (size_t)bh * HD * SEQ;
    const __nv_bfloat16* Vl = g_vtlo + (size_t)bh * HD * SEQ;
    const float cscale = g_scale[h] * 0.04419417382415922f;  // 1/sqrt(512)

    // ---- stage Q tile, lift fragments (region reused by buf0 afterwards)
    uint32_t qhi[4][4], qlo[4][4];
    {
        __nv_bfloat16* Qshi = (__nv_bfloat16*)(sm + ATT_T);
        __nv_bfloat16* Qslo = (__nv_bfloat16*)(sm + ATT_T + 18432);
#pragma unroll
        for (int it = 0; it < 8; ++it) {
            int id = it * 256 + tid;
            int arr = id >> 10, rr = (id >> 3) & 127, gg = id & 7;
            const __nv_bfloat16* src =
                (arr ? Ql : Qh) + (size_t)(q0 + rr) * HD + gg * 8;
            *(uint4*)((arr ? Qslo : Qshi) + rr * ALDT + gg * 8) =
                *(const uint4*)src;
        }
        __syncthreads();
        const int arow = lane & 15, acol = (lane >> 4) * 8;
        uint32_t qa = smb + ATT_T + ((wid * 16 + arow) * ALDT + acol) * 2;
#pragma unroll
        for (int ks = 0; ks < 4; ++ks) {
            ldm_x4(qhi[ks], qa + ks * 32);
            ldm_x4(qlo[ks], qa + ks * 32 + 18432);
        }
        __syncthreads();
    }

    float m0r = -1e30f, m1r = -1e30f, l0r = 0.0f, l1r = 0.0f;
    float Oa[8][4] = {};
    const int qi0 = wid * 16 + gr;

    // prologue: issue tile 0 into buf 0
    {
        uint32_t base = smb + ATT_T;
#pragma unroll
        for (int it = 0; it < 8; ++it) {
            int id = it * 256 + tid;
            int tile = id >> 9, idx = id & 511;
            int rr = idx >> 3, gg = idx & 7;
            const __nv_bfloat16* src;
            if (tile == 0)      src = Kh + (size_t)rr * HD + gg * 8;
            else if (tile == 1) src = Kl + (size_t)rr * HD + gg * 8;
            else if (tile == 2) src = Vh + (size_t)rr * SEQ + gg * 8;
            else                src = Vl + (size_t)rr * SEQ + gg * 8;
            cp16(base + tile * 9216 + rr * 144 + gg * 16, src);
        }
        if (tid < 192)
            cp4(smb + ATT_SG + tid * 4,
                &g_sig[h * RPE_LEN + q0 + 1984 + tid]);
        CP_COMMIT();
    }

    for (int kt = 0; kt < 32; ++kt) {
        const int cur = kt & 1;
        if (kt + 1 < 32) {
            const int k0n = (kt + 1) * 64;
            uint32_t base = smb + ATT_T + (cur ^ 1) * ATT_BUF;
#pragma unroll
            for (int it = 0; it < 8; ++it) {
                int id = it * 256 + tid;
                int tile = id >> 9, idx = id & 511;
                int rr = idx >> 3, gg = idx & 7;
                const __nv_bfloat16* src;
                if (tile == 0)      src = Kh + (size_t)(k0n + rr) * HD + gg * 8;
                else if (tile == 1) src = Kl + (size_t)(k0n + rr) * HD + gg * 8;
                else if (tile == 2) src = Vh + (size_t)rr * SEQ + k0n + gg * 8;
                else                src = Vl + (size_t)rr * SEQ + k0n + gg * 8;
                cp16(base + tile * 9216 + rr * 144 + gg * 16, src);
            }
            if (tid < 192)
                cp4(smb + ATT_SG + (cur ^ 1) * 768 + tid * 4,
                    &g_sig[h * RPE_LEN + q0 - k0n + 1984 + tid]);
            CP_COMMIT();
            CP_WAIT1();
        } else {
            CP_WAIT0();
        }
        __syncthreads();

        const uint32_t kbase = smb + ATT_T + cur * ATT_BUF;
        const float* sgp = (const float*)(sm + ATT_SG + cur * 768);

        // ---- S = Q K^T (ldmatrix K fragments)
        float p[8][4] = {};
#pragma unroll
        for (int ks = 0; ks < 4; ++ks) {
            const int cc = ks * 16;
#pragma unroll
            for (int pp = 0; pp < 4; ++pp) {
                uint32_t bh4[4], bl4[4];
                uint32_t adr =
                    kbase + ((pp * 16 + b_roff) * ALDT + cc + b_koff) * 2;
                ldm_x4(bh4, adr);
                ldm_x4(bl4, adr + 9216);
#pragma unroll
                for (int q = 0; q < 2; ++q) {
                    int nt = 2 * pp + q;
                    uint32_t bh2[2] = {bh4[2 * q], bh4[2 * q + 1]};
                    uint32_t bl2[2] = {bl4[2 * q], bl4[2 * q + 1]};
                    mma_bf16(p[nt], qhi[ks], bh2);
                    mma_bf16(p[nt], qhi[ks], bl2);
                    mma_bf16(p[nt], qlo[ks], bh2);
                }
            }
        }

        // ---- scale + RPE bias + online softmax
        float rmax0 = -1e30f, rmax1 = -1e30f;
#pragma unroll
        for (int nt = 0; nt < 8; ++nt) {
            int kj = nt * 8 + tg * 2;
            p[nt][0] = p[nt][0] * cscale + sgp[qi0 - kj + 63];
            p[nt][1] = p[nt][1] * cscale + sgp[qi0 - kj + 62];
            p[nt][2] = p[nt][2] * cscale + sgp[qi0 - kj + 71];
            p[nt][3] = p[nt][3] * cscale + sgp[qi0 - kj + 70];
            rmax0 = fmaxf(rmax0, fmaxf(p[nt][0], p[nt][1]));
            rmax1 = fmaxf(rmax1, fmaxf(p[nt][2], p[nt][3]));
        }
#pragma unroll
        for (int off = 1; off <= 2; off <<= 1) {
            rmax0 = fmaxf(rmax0, __shfl_xor_sync(0xffffffffu, rmax0, off));
            rmax1 = fmaxf(rmax1, __shfl_xor_sync(0xffffffffu, rmax1, off));
        }
        float mn0 = fmaxf(m0r, rmax0), mn1 = fmaxf(m1r, rmax1);
        float al0 = __expf(m0r - mn0), al1 = __expf(m1r - mn1);
        float rs0 = 0.0f, rs1 = 0.0f;
#pragma unroll
        for (int nt = 0; nt < 8; ++nt) {
            p[nt][0] = __expf(p[nt][0] - mn0);
            p[nt][1] = __expf(p[nt][1] - mn0);
            p[nt][2] = __expf(p[nt][2] - mn1);
            p[nt][3] = __expf(p[nt][3] - mn1);
            rs0 += p[nt][0] + p[nt][1];
            rs1 += p[nt][2] + p[nt][3];
        }
#pragma unroll
        for (int off = 1; off <= 2; off <<= 1) {
            rs0 += __shfl_xor_sync(0xffffffffu, rs0, off);
            rs1 += __shfl_xor_sync(0xffffffffu, rs1, off);
        }
        l0r = l0r * al0 + rs0;
        l1r = l1r * al1 + rs1;
        m0r = mn0;
        m1r = mn1;
#pragma unroll
        for (int nt = 0; nt < 8; ++nt) {
            Oa[nt][0] *= al0; Oa[nt][1] *= al0;
            Oa[nt][2] *= al1; Oa[nt][3] *= al1;
        }

        // ---- pack P into split A-fragments (register-only)
        uint32_t phi[4][4], plo[4][4];
#pragma unroll
        for (int ks2 = 0; ks2 < 4; ++ks2) {
            int ntA = 2 * ks2, ntB = 2 * ks2 + 1;
            split2(p[ntA][0], p[ntA][1], phi[ks2][0], plo[ks2][0]);
            split2(p[ntA][2], p[ntA][3], phi[ks2][1], plo[ks2][1]);
            split2(p[ntB][0], p[ntB][1], phi[ks2][2], plo[ks2][2]);
            split2(p[ntB][2], p[ntB][3], phi[ks2][3], plo[ks2][3]);
        }

        // ---- O += P V (ldmatrix V fragments)
#pragma unroll
        for (int ks2 = 0; ks2 < 4; ++ks2) {
            const int cc = ks2 * 16;
#pragma unroll
            for (int pp = 0; pp < 4; ++pp) {
                uint32_t vh4[4], vl4[4];
                uint32_t adr = kbase + 18432 +
                    ((pp * 16 + b_roff) * ALDT + cc + b_koff) * 2;
                ldm_x4(vh4, adr);
                ldm_x4(vl4, adr + 9216);
#pragma unroll
                for (int q = 0; q < 2; ++q) {
                    int nt = 2 * pp + q;
                    uint32_t vh2[2] = {vh4[2 * q], vh4[2 * q + 1]};
                    uint32_t vl2[2] = {vl4[2 * q], vl4[2 * q + 1]};
                    mma_bf16(Oa[nt], phi[ks2], vh2);
                    mma_bf16(Oa[nt], phi[ks2], vl2);
                    mma_bf16(Oa[nt], plo[ks2], vh2);
                }
            }
        }
        __syncthreads();
    }

    // ---- normalize, write split-bf16 concat-head output
    float inv0 = 1.0f / l0r, inv1 = 1.0f / l1r;
    int qrow = q0 + qi0;
#pragma unroll
    for (int nt = 0; nt < 8; ++nt) {
        int col = h * HD + nt * 8 + tg * 2;
        size_t off0 = (size_t)(b * SEQ + qrow) * DM + col;
        size_t off1 = (size_t)(b * SEQ + qrow + 8) * DM + col;
        uint32_t hp, lp;
        split2(Oa[nt][0] * inv0, Oa[nt][1] * inv0, hp, lp);
        *(uint32_t*)(g_ohi + off0) = hp;
        *(uint32_t*)(g_olo + off0) = lp;
        split2(Oa[nt][2] * inv1, Oa[nt][3] * inv1, hp, lp);
        *(uint32_t*)(g_ohi + off1) = hp;
        *(uint32_t*)(g_olo + off1) = lp;
    }
}

// ---------------------------------------------------------------------------
extern "C" void kernel_launch(void* const* d_in, const int* in_sizes, int n_in,
                              void* d_out, int out_size) {
    (void)in_sizes; (void)n_in; (void)out_size;
    const float* query = (const float*)d_in[0];
    const float* Wq = (const float*)d_in[1];
    const float* bq = (const float*)d_in[2];
    const float* Wk = (const float*)d_in[3];
    const float* bk = (const float*)d_in[4];
    const float* Wv = (const float*)d_in[5];
    const float* bv = (const float*)d_in[6];
    const float* Wp = (const float*)d_in[7];
    const float* bp = (const float*)d_in[8];
    const float* ls = (const float*)d_in[9];
    const float* rpe = (const float*)d_in[10];

    cudaFuncSetAttribute(qkv_mm_kernel_b,
                         cudaFuncAttributeMaxDynamicSharedMemorySize,
                         GEMM_SMEM_BYTES);
    cudaFuncSetAttribute(oproj_mm_kernel,
                         cudaFuncAttributeMaxDynamicSharedMemorySize,
                         GEMM_SMEM_BYTES);
    cudaFuncSetAttribute(attn_mm_kernel,
                         cudaFuncAttributeMaxDynamicSharedMemorySize,
                         ATTN_SMEM_BYTES);

    prep_kernel<<<(NH * RPE_LEN + 255) / 256, 256>>>(rpe, ls);
    split_kernel<<<4096, 256>>>((const float4*)query, 0, 0, ROWS * DM / 4);
    split_kernel<<<256, 256>>>((const float4*)Wq, 1, 0 * DM * DM / 4, DM * DM / 4);
    split_kernel<<<256, 256>>>((const float4*)Wk, 1, 1 * DM * DM / 4, DM * DM / 4);
    split_kernel<<<256, 256>>>((const float4*)Wv, 1, 2 * DM * DM / 4, DM * DM / 4);
    split_kernel<<<256, 256>>>((const float4*)Wp, 1, 3 * DM * DM / 4, DM * DM / 4);

    qkv_mm_kernel_b<<<dim3(ROWS / 128, DM / 128, 3), 256, GEMM_SMEM_BYTES>>>(
        bq, bk, bv);
    attn_mm_kernel<<<dim3(SEQ / 128, BATCH * NH), 256, ATTN_SMEM_BYTES>>>();
    oproj_mm_kernel<<<dim3(ROWS / 128, DM / 128), 256, GEMM_SMEM_BYTES>>>(
        bp, (float*)d_out);
}

// round 15
// speedup vs baseline: 1.3735x; 1.0416x over previous
#include <cuda_runtime.h>
#include <cuda_bf16.h>
#include <math.h>
#include <stdint.h>

#define BATCH 4
#define SEQ 2048
#define DM 512
#define NH 8
#define HD 64
#define ROWS (BATCH*SEQ)
#define RPE_LEN (2*SEQ-1)
#define QKV_ELEMS (BATCH*NH*SEQ*HD)

// --------- static device scratch (no allocations allowed) ------------------
__device__ __nv_bfloat16 g_xhi[ROWS*DM],   g_xlo[ROWS*DM];
__device__ __nv_bfloat16 g_whi[4*DM*DM],   g_wlo[4*DM*DM];
__device__ __nv_bfloat16 g_qhi[QKV_ELEMS], g_qlo[QKV_ELEMS];
__device__ __nv_bfloat16 g_khi[QKV_ELEMS], g_klo[QKV_ELEMS];
__device__ __nv_bfloat16 g_vthi[QKV_ELEMS], g_vtlo[QKV_ELEMS];   // (b,h,d,s)
__device__ __nv_bfloat16 g_ohi[ROWS*DM],   g_olo[ROWS*DM];
__device__ float g_sig[NH*RPE_LEN];       // exp(sigmoid(rpe)), head-major
__device__ float g_scale[NH];

// ===========================================================================
// helpers
// ===========================================================================
__device__ __forceinline__ uint32_t smem_u32(const void* p) {
    uint32_t a;
    asm("{ .reg .u64 t; cvta.to.shared.u64 t, %1; cvt.u32.u64 %0, t; }"
        : "=r"(a) : "l"(p));
    return a;
}
__device__ __forceinline__ void mma_bf16(float d[4], const uint32_t a[4],
                                         const uint32_t b[2]) {
    asm volatile(
        "mma.sync.aligned.m16n8k16.row.col.f32.bf16.bf16.f32 "
        "{%0,%1,%2,%3}, {%4,%5,%6,%7}, {%8,%9}, {%0,%1,%2,%3};"
        : "+f"(d[0]), "+f"(d[1]), "+f"(d[2]), "+f"(d[3])
        : "r"(a[0]), "r"(a[1]), "r"(a[2]), "r"(a[3]), "r"(b[0]), "r"(b[1]));
}
__device__ __forceinline__ void ldm_x4(uint32_t r[4], uint32_t a) {
    asm volatile(
        "ldmatrix.sync.aligned.m8n8.x4.shared.b16 {%0,%1,%2,%3}, [%4];"
        : "=r"(r[0]), "=r"(r[1]), "=r"(r[2]), "=r"(r[3]) : "r"(a));
}
__device__ __forceinline__ uint32_t pack2bf(float x0, float x1) {
    uint32_t r;
    asm("cvt.rn.bf16x2.f32 %0, %1, %2;" : "=r"(r) : "f"(x1), "f"(x0));
    return r;
}
__device__ __forceinline__ void split2(float x0, float x1,
                                       uint32_t& hp, uint32_t& lp) {
    hp = pack2bf(x0, x1);
    float h0 = __uint_as_float(hp << 16);
    float h1 = __uint_as_float(hp & 0xFFFF0000u);
    lp = pack2bf(x0 - h0, x1 - h1);
}
__device__ __forceinline__ void cp16(uint32_t dst, const void* src) {
    asm volatile("cp.async.cg.shared.global [%0], [%1], 16;"
                 :: "r"(dst), "l"(src));
}
__device__ __forceinline__ void cp4(uint32_t dst, const void* src) {
    asm volatile("cp.async.ca.shared.global [%0], [%1], 4;"
                 :: "r"(dst), "l"(src));
}
#define CP_COMMIT() asm volatile("cp.async.commit_group;" ::: "memory")
#define CP_WAIT1()  asm volatile("cp.async.wait_group 1;" ::: "memory")
#define CP_WAIT0()  asm volatile("cp.async.wait_group 0;" ::: "memory")

// ===========================================================================
// Kernel 0a: exp(sigmoid(rpe)) table + per-head scale
// ===========================================================================
__global__ void prep_kernel(const float* __restrict__ rpe,
                            const float* __restrict__ ls) {
    int i = blockIdx.x * blockDim.x + threadIdx.x;
    if (i < NH * RPE_LEN) {
        int hh = i % NH;
        int p  = i / NH;
        float x = rpe[p * NH + hh];
        float sg = 1.0f / (1.0f + __expf(-x));
        g_sig[hh * RPE_LEN + p] = __expf(sg);
    }
    if (i < NH) g_scale[i] = __expf(fminf(ls[i], 4.6051701859880914f));
}

// ===========================================================================
// Kernel 0b: fp32 -> (hi, lo) bf16 split. dst_sel: 0 = X, 1 = W pool.
// ===========================================================================
__global__ void split_kernel(const float4* __restrict__ src, int dst_sel,
                             int dst_off4, int n4) {
    int i = blockIdx.x * blockDim.x + threadIdx.x;
    if (i >= n4) return;
    uint2* hi = (dst_sel == 0) ? (uint2*)g_xhi : (uint2*)g_whi;
    uint2* lo = (dst_sel == 0) ? (uint2*)g_xlo : (uint2*)g_wlo;
    float4 f = src[i];
    uint32_t h0, l0, h1, l1;
    split2(f.x, f.y, h0, l0);
    split2(f.z, f.w, h1, l1);
    hi[dst_off4 + i] = make_uint2(h0, h1);
    lo[dst_off4 + i] = make_uint2(l0, l1);
}

// ===========================================================================
// Pre-split 128x128 GEMM tile, K=512 in 8 chunks of 64, double-buffered,
// ldmatrix fragment loads. 8 warps 2(m) x 4(n), warp tile 64x32.
// buffer layout (bytes): Ahi 0, Alo 18432, Bhi 36864, Blo 55296 (LDTG=72)
// ===========================================================================
#define LDTG 72
#define CS_LD 130
#define G_BIAS 0
#define G_T    512
#define G_BUF  73728
#define GEMM_SMEM_BYTES (512 + 2*73728)   // 147968

__device__ __forceinline__ void gemm_tile_ps(
    const __nv_bfloat16* __restrict__ Ahg, const __nv_bfloat16* __restrict__ Alg,
    const __nv_bfloat16* __restrict__ Bhg, const __nv_bfloat16* __restrict__ Blg,
    uint32_t smb, int tid, float* Cs) {
    const int wid = tid >> 5, lane = tid & 31;
    const int gr = lane >> 2, tg = lane & 3;
    const int wm = (wid >> 2) * 64;
    const int wn = (wid & 3) * 32;
    const int arow = lane & 15, acol = (lane >> 4) * 8;
    const int b_roff = (((lane >> 3) >> 1) & 1) * 8 + (lane & 7);
    const int b_koff = ((lane >> 3) & 1) * 8;

    float acc[4][4][4] = {};

    {
        uint32_t base = smb + G_T;
#pragma unroll
        for (int it = 0; it < 16; ++it) {
            int id = it * 256 + tid;
            int tile = id >> 10, idx = id & 1023;
            int rr = idx >> 3, gg = idx & 7;
            const __nv_bfloat16* src =
                (tile == 0 ? Ahg : tile == 1 ? Alg : tile == 2 ? Bhg : Blg) +
                (size_t)rr * DM + gg * 8;
            cp16(base + tile * 18432 + rr * 144 + gg * 16, src);
        }
        CP_COMMIT();
    }

    for (int c = 0; c < 8; ++c) {
        const int cur = c & 1;
        if (c + 1 < 8) {
            const int k0 = (c + 1) * 64;
            uint32_t base = smb + G_T + (cur ^ 1) * G_BUF;
#pragma unroll
            for (int it = 0; it < 16; ++it) {
                int id = it * 256 + tid;
                int tile = id >> 10, idx = id & 1023;
                int rr = idx >> 3, gg = idx & 7;
                const __nv_bfloat16* src =
                    (tile == 0 ? Ahg : tile == 1 ? Alg : tile == 2 ? Bhg : Blg)
                    + (size_t)rr * DM + k0 + gg * 8;
                cp16(base + tile * 18432 + rr * 144 + gg * 16, src);
            }
            CP_COMMIT();
            CP_WAIT1();
        } else {
            CP_WAIT0();
        }
        __syncthreads();

        const uint32_t base = smb + G_T + cur * G_BUF;
#pragma unroll
        for (int ks = 0; ks < 4; ++ks) {
            const int cc = ks * 16;
            uint32_t ahi[4][4], alo[4][4];
#pragma unroll
            for (int mt = 0; mt < 4; ++mt) {
                uint32_t aadr =
                    base + ((wm + mt * 16 + arow) * LDTG + cc + acol) * 2;
                ldm_x4(ahi[mt], aadr);
                ldm_x4(alo[mt], aadr + 18432);
            }
#pragma unroll
            for (int pp = 0; pp < 2; ++pp) {
                uint32_t bh4[4], bl4[4];
                uint32_t badr = base + 36864 +
                    ((wn + pp * 16 + b_roff) * LDTG + cc + b_koff) * 2;
                ldm_x4(bh4, badr);
                ldm_x4(bl4, badr + 18432);
#pragma unroll
                for (int q = 0; q < 2; ++q) {
                    int nt = 2 * pp + q;
                    uint32_t bh2[2] = {bh4[2 * q], bh4[2 * q + 1]};
                    uint32_t bl2[2] = {bl4[2 * q], bl4[2 * q + 1]};
#pragma unroll
                    for (int mt = 0; mt < 4; ++mt) {
                        mma_bf16(acc[mt][nt], ahi[mt], bh2);
                        mma_bf16(acc[mt][nt], ahi[mt], bl2);
                        mma_bf16(acc[mt][nt], alo[mt], bh2);
                    }
                }
            }
        }
        __syncthreads();
    }

#pragma unroll
    for (int mt = 0; mt < 4; ++mt)
#pragma unroll
        for (int nt = 0; nt < 4; ++nt) {
            int r  = wm + mt * 16 + gr;
            int cl = wn + nt * 8 + tg * 2;
            Cs[cl * CS_LD + r]           = acc[mt][nt][0];
            Cs[(cl + 1) * CS_LD + r]     = acc[mt][nt][1];
            Cs[cl * CS_LD + r + 8]       = acc[mt][nt][2];
            Cs[(cl + 1) * CS_LD + r + 8] = acc[mt][nt][3];
        }
    __syncthreads();
}

// ===========================================================================
// Kernel 2: QKV projections. grid = (64, 4, 3), block 256.
// Q is pre-scaled by g_scale[h]/sqrt(512) so attention needs no scaling.
// Writes Q,K row-major split-bf16; V transposed (b,h,d,s) split-bf16.
// ===========================================================================
__global__ __launch_bounds__(256) void qkv_mm_kernel_b(
    const float* __restrict__ bq, const float* __restrict__ bk,
    const float* __restrict__ bv) {
    extern __shared__ char sm[];
    const uint32_t smb = smem_u32(sm);
    const int tid = threadIdx.x;
    const int row0 = blockIdx.x * 128;
    const int n0   = blockIdx.y * 128;
    const int which = blockIdx.z;
    const float* bias = (which == 0) ? bq : (which == 1) ? bk : bv;
    float* bsm = (float*)(sm + G_BIAS);
    if (tid < 128) bsm[tid] = bias[n0 + tid];

    float* Cs = (float*)(sm + G_T);
    gemm_tile_ps(g_xhi + (size_t)row0 * DM, g_xlo + (size_t)row0 * DM,
                 g_whi + (size_t)which * DM * DM + (size_t)n0 * DM,
                 g_wlo + (size_t)which * DM * DM + (size_t)n0 * DM,
                 smb, tid, Cs);

    const int b   = row0 >> 11;
    const int s_b = row0 & (SEQ - 1);
    if (which < 2) {
        __nv_bfloat16* hiO = which ? g_khi : g_qhi;
        __nv_bfloat16* loO = which ? g_klo : g_qlo;
        const int d0base = n0 >> 3;
#pragma unroll
        for (int it = 0; it < 16; ++it) {
            int id  = it * 256 + tid;
            int g   = id & 3;
            int h   = (id >> 2) & 7;
            int row = id >> 5;
            float qs = (which == 0)
                           ? g_scale[h] * 0.04419417382415922f
                           : 1.0f;
            float v[4];
#pragma unroll
            for (int u = 0; u < 4; ++u) {
                int j = h + 32 * g + 8 * u;
                v[u] = (Cs[j * CS_LD + row] + bsm[j]) * qs;
            }
            int s  = s_b + row;
            int d0 = d0base + 4 * g;
            size_t off = ((size_t)((b * NH + h) * SEQ + s)) * HD + d0;
            uint32_t h0, l0, h1, l1;
            split2(v[0], v[1], h0, l0);
            split2(v[2], v[3], h1, l1);
            *(uint2*)(hiO + off) = make_uint2(h0, h1);
            *(uint2*)(loO + off) = make_uint2(l0, l1);
        }
    } else {
        // V transposed: vt[(b*NH+h)*HD + d][s]
#pragma unroll
        for (int it = 0; it < 16; ++it) {
            int id   = it * 256 + tid;
            int rblk = id & 31;
            int j    = id >> 5;
            int wr   = n0 + j;
            int h    = wr & 7;
            int d    = wr >> 3;
            float bj = bsm[j];
            float2 c0 = *(float2*)&Cs[j * CS_LD + rblk * 4];
            float2 c1 = *(float2*)&Cs[j * CS_LD + rblk * 4 + 2];
            float v0 = c0.x + bj, v1 = c0.y + bj;
            float v2 = c1.x + bj, v3 = c1.y + bj;
            size_t off =
                ((size_t)((b * NH + h) * HD + d)) * SEQ + s_b + rblk * 4;
            uint32_t h0, l0, h1, l1;
            split2(v0, v1, h0, l0);
            split2(v2, v3, h1, l1);
            *(uint2*)(g_vthi + off) = make_uint2(h0, h1);
            *(uint2*)(g_vtlo + off) = make_uint2(l0, l1);
        }
    }
}

// ===========================================================================
// Kernel 4: output projection. grid = (64, 4), block 256. fp32 out.
// ===========================================================================
__global__ __launch_bounds__(256) void oproj_mm_kernel(
    const float* __restrict__ bp, float* __restrict__ out) {
    extern __shared__ char sm[];
    const uint32_t smb = smem_u32(sm);
    const int tid = threadIdx.x;
    const int row0 = blockIdx.x * 128;
    const int n0   = blockIdx.y * 128;

    float* bsm = (float*)(sm + G_BIAS);
    if (tid < 128) bsm[tid] = bp[n0 + tid];
    float* Cs = (float*)(sm + G_T);

    gemm_tile_ps(g_ohi + (size_t)row0 * DM, g_olo + (size_t)row0 * DM,
                 g_whi + (size_t)3 * DM * DM + (size_t)n0 * DM,
                 g_wlo + (size_t)3 * DM * DM + (size_t)n0 * DM,
                 smb, tid, Cs);

#pragma unroll
    for (int it = 0; it < 16; ++it) {
        int id  = it * 256 + tid;
        int q4  = id & 31;
        int row = id >> 5;
        float v[4];
#pragma unroll
        for (int u = 0; u < 4; ++u) {
            int j = 4 * q4 + u;
            v[u] = Cs[j * CS_LD + row] + bsm[j];
        }
        *(float4*)(out + (size_t)(row0 + row) * DM + n0 + 4 * q4) =
            make_float4(v[0], v[1], v[2], v[3]);
    }
}

// ===========================================================================
// Kernel 3: flash attention, NO-MAX softmax (logits bounded), pre-split
// inputs, cp.async double-buffered, ldmatrix fragments.
// grid = (16, 32), block 256.
// p = exp(s) * expsig[idx]; l accumulated per-thread, reduced once at end.
// ===========================================================================
#define ALDT 72
#define ATT_SG 0
#define ATT_T  1536
#define ATT_BUF 36864
#define ATTN_SMEM_BYTES (1536 + 2*36864)

__global__ __launch_bounds__(256) void attn_mm_kernel() {
    extern __shared__ char sm[];
    const uint32_t smb = smem_u32(sm);
    const int tid = threadIdx.x, wid = tid >> 5, lane = tid & 31;
    const int gr = lane >> 2, tg = lane & 3;
    const int b_roff = (((lane >> 3) >> 1) & 1) * 8 + (lane & 7);
    const int b_koff = ((lane >> 3) & 1) * 8;
    const int bh = blockIdx.y, b = bh >> 3, h = bh & 7;
    const int q0 = blockIdx.x * 128;
    const __nv_bfloat16* Qh = g_qhi + (size_t)bh * SEQ * HD;
    const __nv_bfloat16* Ql = g_qlo + (size_t)bh * SEQ * HD;
    const __nv_bfloat16* Kh = g_khi + (size_t)bh * SEQ * HD;
    const __nv_bfloat16* Kl = g_klo + (size_t)bh * SEQ * HD;
    const __nv_bfloat16* Vh = g_vthi + (size_t)bh * HD * SEQ;
    const __nv_bfloat16* Vl = g_vtlo + (size_t)bh * HD * SEQ;

    // ---- stage Q tile, lift fragments (region reused by buf0 afterwards)
    uint32_t qhi[4][4], qlo[4][4];
    {
        __nv_bfloat16* Qshi = (__nv_bfloat16*)(sm + ATT_T);
        __nv_bfloat16* Qslo = (__nv_bfloat16*)(sm + ATT_T + 18432);
#pragma unroll
        for (int it = 0; it < 8; ++it) {
            int id = it * 256 + tid;
            int arr = id >> 10, rr = (id >> 3) & 127, gg = id & 7;
            const __nv_bfloat16* src =
                (arr ? Ql : Qh) + (size_t)(q0 + rr) * HD + gg * 8;
            *(uint4*)((arr ? Qslo : Qshi) + rr * ALDT + gg * 8) =
                *(const uint4*)src;
        }
        __syncthreads();
        const int arow = lane & 15, acol = (lane >> 4) * 8;
        uint32_t qa = smb + ATT_T + ((wid * 16 + arow) * ALDT + acol) * 2;
#pragma unroll
        for (int ks = 0; ks < 4; ++ks) {
            ldm_x4(qhi[ks], qa + ks * 32);
            ldm_x4(qlo[ks], qa + ks * 32 + 18432);
        }
        __syncthreads();
    }

    float l0r = 0.0f, l1r = 0.0f;
    float Oa[8][4] = {};
    const int qi0 = wid * 16 + gr;

    // prologue: issue tile 0 into buf 0
    {
        uint32_t base = smb + ATT_T;
#pragma unroll
        for (int it = 0; it < 8; ++it) {
            int id = it * 256 + tid;
            int tile = id >> 9, idx = id & 511;
            int rr = idx >> 3, gg = idx & 7;
            const __nv_bfloat16* src;
            if (tile == 0)      src = Kh + (size_t)rr * HD + gg * 8;
            else if (tile == 1) src = Kl + (size_t)rr * HD + gg * 8;
            else if (tile == 2) src = Vh + (size_t)rr * SEQ + gg * 8;
            else                src = Vl + (size_t)rr * SEQ + gg * 8;
            cp16(base + tile * 9216 + rr * 144 + gg * 16, src);
        }
        if (tid < 192)
            cp4(smb + ATT_SG + tid * 4,
                &g_sig[h * RPE_LEN + q0 + 1984 + tid]);
        CP_COMMIT();
    }

    for (int kt = 0; kt < 32; ++kt) {
        const int cur = kt & 1;
        if (kt + 1 < 32) {
            const int k0n = (kt + 1) * 64;
            uint32_t base = smb + ATT_T + (cur ^ 1) * ATT_BUF;
#pragma unroll
            for (int it = 0; it < 8; ++it) {
                int id = it * 256 + tid;
                int tile = id >> 9, idx = id & 511;
                int rr = idx >> 3, gg = idx & 7;
                const __nv_bfloat16* src;
                if (tile == 0)      src = Kh + (size_t)(k0n + rr) * HD + gg * 8;
                else if (tile == 1) src = Kl + (size_t)(k0n + rr) * HD + gg * 8;
                else if (tile == 2) src = Vh + (size_t)rr * SEQ + k0n + gg * 8;
                else                src = Vl + (size_t)rr * SEQ + k0n + gg * 8;
                cp16(base + tile * 9216 + rr * 144 + gg * 16, src);
            }
            if (tid < 192)
                cp4(smb + ATT_SG + (cur ^ 1) * 768 + tid * 4,
                    &g_sig[h * RPE_LEN + q0 - k0n + 1984 + tid]);
            CP_COMMIT();
            CP_WAIT1();
        } else {
            CP_WAIT0();
        }
        __syncthreads();

        const uint32_t kbase = smb + ATT_T + cur * ATT_BUF;
        const float* sgp = (const float*)(sm + ATT_SG + cur * 768);

        // ---- S = Q K^T (ldmatrix K fragments)
        float p[8][4] = {};
#pragma unroll
        for (int ks = 0; ks < 4; ++ks) {
            const int cc = ks * 16;
#pragma unroll
            for (int pp = 0; pp < 4; ++pp) {
                uint32_t bh4[4], bl4[4];
                uint32_t adr =
                    kbase + ((pp * 16 + b_roff) * ALDT + cc + b_koff) * 2;
                ldm_x4(bh4, adr);
                ldm_x4(bl4, adr + 9216);
#pragma unroll
                for (int q = 0; q < 2; ++q) {
                    int nt = 2 * pp + q;
                    uint32_t bh2[2] = {bh4[2 * q], bh4[2 * q + 1]};
                    uint32_t bl2[2] = {bl4[2 * q], bl4[2 * q + 1]};
                    mma_bf16(p[nt], qhi[ks], bh2);
                    mma_bf16(p[nt], qhi[ks], bl2);
                    mma_bf16(p[nt], qlo[ks], bh2);
                }
            }
        }

        // ---- no-max softmax: p = exp(s) * expsig(bias); accumulate l
#pragma unroll
        for (int nt = 0; nt < 8; ++nt) {
            int kj = nt * 8 + tg * 2;
            p[nt][0] = __expf(p[nt][0]) * sgp[qi0 - kj + 63];
            p[nt][1] = __expf(p[nt][1]) * sgp[qi0 - kj + 62];
            p[nt][2] = __expf(p[nt][2]) * sgp[qi0 - kj + 71];
            p[nt][3] = __expf(p[nt][3]) * sgp[qi0 - kj + 70];
            l0r += p[nt][0] + p[nt][1];
            l1r += p[nt][2] + p[nt][3];
        }

        // ---- pack P into split A-fragments (register-only)
        uint32_t phi[4][4], plo[4][4];
#pragma unroll
        for (int ks2 = 0; ks2 < 4; ++ks2) {
            int ntA = 2 * ks2, ntB = 2 * ks2 + 1;
            split2(p[ntA][0], p[ntA][1], phi[ks2][0], plo[ks2][0]);
            split2(p[ntA][2], p[ntA][3], phi[ks2][1], plo[ks2][1]);
            split2(p[ntB][0], p[ntB][1], phi[ks2][2], plo[ks2][2]);
            split2(p[ntB][2], p[ntB][3], phi[ks2][3], plo[ks2][3]);
        }

        // ---- O += P V (ldmatrix V fragments)
#pragma unroll
        for (int ks2 = 0; ks2 < 4; ++ks2) {
            const int cc = ks2 * 16;
#pragma unroll
            for (int pp = 0; pp < 4; ++pp) {
                uint32_t vh4[4], vl4[4];
                uint32_t adr = kbase + 18432 +
                    ((pp * 16 + b_roff) * ALDT + cc + b_koff) * 2;
                ldm_x4(vh4, adr);
                ldm_x4(vl4, adr + 9216);
#pragma unroll
                for (int q = 0; q < 2; ++q) {
                    int nt = 2 * pp + q;
                    uint32_t vh2[2] = {vh4[2 * q], vh4[2 * q + 1]};
                    uint32_t vl2[2] = {vl4[2 * q], vl4[2 * q + 1]};
                    mma_bf16(Oa[nt], phi[ks2], vh2);
                    mma_bf16(Oa[nt], phi[ks2], vl2);
                    mma_bf16(Oa[nt], plo[ks2], vh2);
                }
            }
        }
        __syncthreads();
    }

    // ---- single final row-sum reduction across the 4 tg lanes
#pragma unroll
    for (int off = 1; off <= 2; off <<= 1) {
        l0r += __shfl_xor_sync(0xffffffffu, l0r, off);
        l1r += __shfl_xor_sync(0xffffffffu, l1r, off);
    }

    // ---- normalize, write split-bf16 concat-head output
    float inv0 = 1.0f / l0r, inv1 = 1.0f / l1r;
    int qrow = q0 + qi0;
#pragma unroll
    for (int nt = 0; nt < 8; ++nt) {
        int col = h * HD + nt * 8 + tg * 2;
        size_t off0 = (size_t)(b * SEQ + qrow) * DM + col;
        size_t off1 = (size_t)(b * SEQ + qrow + 8) * DM + col;
        uint32_t hp, lp;
        split2(Oa[nt][0] * inv0, Oa[nt][1] * inv0, hp, lp);
        *(uint32_t*)(g_ohi + off0) = hp;
        *(uint32_t*)(g_olo + off0) = lp;
        split2(Oa[nt][2] * inv1, Oa[nt][3] * inv1, hp, lp);
        *(uint32_t*)(g_ohi + off1) = hp;
        *(uint32_t*)(g_olo + off1) = lp;
    }
}

// ---------------------------------------------------------------------------
extern "C" void kernel_launch(void* const* d_in, const int* in_sizes, int n_in,
                              void* d_out, int out_size) {
    (void)in_sizes; (void)n_in; (void)out_size;
    const float* query = (const float*)d_in[0];
    const float* Wq = (const float*)d_in[1];
    const float* bq = (const float*)d_in[2];
    const float* Wk = (const float*)d_in[3];
    const float* bk = (const float*)d_in[4];
    const float* Wv = (const float*)d_in[5];
    const float* bv = (const float*)d_in[6];
    const float* Wp = (const float*)d_in[7];
    const float* bp = (const float*)d_in[8];
    const float* ls = (const float*)d_in[9];
    const float* rpe = (const float*)d_in[10];

    cudaFuncSetAttribute(qkv_mm_kernel_b,
                         cudaFuncAttributeMaxDynamicSharedMemorySize,
                         GEMM_SMEM_BYTES);
    cudaFuncSetAttribute(oproj_mm_kernel,
                         cudaFuncAttributeMaxDynamicSharedMemorySize,
                         GEMM_SMEM_BYTES);
    cudaFuncSetAttribute(attn_mm_kernel,
                         cudaFuncAttributeMaxDynamicSharedMemorySize,
                         ATTN_SMEM_BYTES);

    prep_kernel<<<(NH * RPE_LEN + 255) / 256, 256>>>(rpe, ls);
    split_kernel<<<4096, 256>>>((const float4*)query, 0, 0, ROWS * DM / 4);
    split_kernel<<<256, 256>>>((const float4*)Wq, 1, 0 * DM * DM / 4, DM * DM / 4);
    split_kernel<<<256, 256>>>((const float4*)Wk, 1, 1 * DM * DM / 4, DM * DM / 4);
    split_kernel<<<256, 256>>>((const float4*)Wv, 1, 2 * DM * DM / 4, DM * DM / 4);
    split_kernel<<<256, 256>>>((const float4*)Wp, 1, 3 * DM * DM / 4, DM * DM / 4);

    qkv_mm_kernel_b<<<dim3(ROWS / 128, DM / 128, 3), 256, GEMM_SMEM_BYTES>>>(
        bq, bk, bv);
    attn_mm_kernel<<<dim3(SEQ / 128, BATCH * NH), 256, ATTN_SMEM_BYTES>>>();
    oproj_mm_kernel<<<dim3(ROWS / 128, DM / 128), 256, GEMM_SMEM_BYTES>>>(
        bp, (float*)d_out);
}

// round 16
// speedup vs baseline: 2.0020x; 1.4576x over previous
#include <cuda_runtime.h>
#include <cuda_fp16.h>
#include <math.h>
#include <stdint.h>

#define BATCH 4
#define SEQ 2048
#define DM 512
#define NH 8
#define HD 64
#define ROWS (BATCH*SEQ)
#define RPE_LEN (2*SEQ-1)
#define QKV_ELEMS (BATCH*NH*SEQ*HD)

// --------- static device scratch (no allocations allowed) ------------------
// A-side operands keep (hi, lo) fp16 split; B-side operands are fp16 hi-only.
__device__ __half g_xhi[ROWS*DM], g_xlo[ROWS*DM];
__device__ __half g_wh[4*DM*DM];                   // Wq,Wk,Wv,Wp fp16
__device__ __half g_qhi[QKV_ELEMS], g_qlo[QKV_ELEMS];
__device__ __half g_kh[QKV_ELEMS];                 // K fp16 (B-side)
__device__ __half g_vth[QKV_ELEMS];                // V^T (b,h,d,s) fp16 (B-side)
__device__ __half g_ohi[ROWS*DM], g_olo[ROWS*DM];
__device__ float g_sig[NH*RPE_LEN];                // exp(sigmoid(rpe))
__device__ float g_scale[NH];

// ===========================================================================
// helpers
// ===========================================================================
__device__ __forceinline__ uint32_t smem_u32(const void* p) {
    uint32_t a;
    asm("{ .reg .u64 t; cvta.to.shared.u64 t, %1; cvt.u32.u64 %0, t; }"
        : "=r"(a) : "l"(p));
    return a;
}
__device__ __forceinline__ void mma_f16(float d[4], const uint32_t a[4],
                                        const uint32_t b[2]) {
    asm volatile(
        "mma.sync.aligned.m16n8k16.row.col.f32.f16.f16.f32 "
        "{%0,%1,%2,%3}, {%4,%5,%6,%7}, {%8,%9}, {%0,%1,%2,%3};"
        : "+f"(d[0]), "+f"(d[1]), "+f"(d[2]), "+f"(d[3])
        : "r"(a[0]), "r"(a[1]), "r"(a[2]), "r"(a[3]), "r"(b[0]), "r"(b[1]));
}
__device__ __forceinline__ void ldm_x4(uint32_t r[4], uint32_t a) {
    asm volatile(
        "ldmatrix.sync.aligned.m8n8.x4.shared.b16 {%0,%1,%2,%3}, [%4];"
        : "=r"(r[0]), "=r"(r[1]), "=r"(r[2]), "=r"(r[3]) : "r"(a));
}
__device__ __forceinline__ uint32_t pack2h(float x0, float x1) {
    __half2 h = __floats2half2_rn(x0, x1);   // .x = x0 (low half)
    return *(uint32_t*)&h;
}
__device__ __forceinline__ void split2h(float x0, float x1,
                                        uint32_t& hp, uint32_t& lp) {
    hp = pack2h(x0, x1);
    __half2 h = *(__half2*)&hp;
    float2 hf = __half22float2(h);
    lp = pack2h(x0 - hf.x, x1 - hf.y);
}
__device__ __forceinline__ void cp16(uint32_t dst, const void* src) {
    asm volatile("cp.async.cg.shared.global [%0], [%1], 16;"
                 :: "r"(dst), "l"(src));
}
__device__ __forceinline__ void cp4(uint32_t dst, const void* src) {
    asm volatile("cp.async.ca.shared.global [%0], [%1], 4;"
                 :: "r"(dst), "l"(src));
}
#define CP_COMMIT() asm volatile("cp.async.commit_group;" ::: "memory")
#define CP_WAIT1()  asm volatile("cp.async.wait_group 1;" ::: "memory")
#define CP_WAIT0()  asm volatile("cp.async.wait_group 0;" ::: "memory")

// ===========================================================================
// Kernel 0a: exp(sigmoid(rpe)) table + per-head scale
// ===========================================================================
__global__ void prep_kernel(const float* __restrict__ rpe,
                            const float* __restrict__ ls) {
    int i = blockIdx.x * blockDim.x + threadIdx.x;
    if (i < NH * RPE_LEN) {
        int hh = i % NH;
        int p  = i / NH;
        float x = rpe[p * NH + hh];
        float sg = 1.0f / (1.0f + __expf(-x));
        g_sig[hh * RPE_LEN + p] = __expf(sg);
    }
    if (i < NH) g_scale[i] = __expf(fminf(ls[i], 4.6051701859880914f));
}

// ===========================================================================
// Kernel 0b: X fp32 -> (hi, lo) fp16 split
// ===========================================================================
__global__ void split_x_kernel(const float4* __restrict__ src) {
    int i = blockIdx.x * blockDim.x + threadIdx.x;
    float4 f = src[i];
    uint32_t h0, l0, h1, l1;
    split2h(f.x, f.y, h0, l0);
    split2h(f.z, f.w, h1, l1);
    ((uint2*)g_xhi)[i] = make_uint2(h0, h1);
    ((uint2*)g_xlo)[i] = make_uint2(l0, l1);
}

// ===========================================================================
// Kernel 0c: W fp32 -> fp16 (hi only). grid (256, 4).
// ===========================================================================
__global__ void conv_w_kernel(const float4* __restrict__ w0,
                              const float4* __restrict__ w1,
                              const float4* __restrict__ w2,
                              const float4* __restrict__ w3) {
    int i = blockIdx.x * blockDim.x + threadIdx.x;
    int which = blockIdx.y;
    const float4* w = (which == 0) ? w0 : (which == 1) ? w1
                     : (which == 2) ? w2 : w3;
    float4 f = w[i];
    ((uint2*)g_wh)[(size_t)which * (DM * DM / 4) + i] =
        make_uint2(pack2h(f.x, f.y), pack2h(f.z, f.w));
}

// ===========================================================================
// fp16 2-term 128x128 GEMM tile: D = (Ahi+Alo) * Bhi^T, K=512, chunks of 64,
// double-buffered cp.async, ldmatrix. 8 warps 2(m) x 4(n), warp tile 64x32.
// buffer (bytes): Ahi 0, Alo 18432, Bhi 36864  (LDTG=72)
// ===========================================================================
#define LDTG 72
#define CS_LD 130
#define G_BIAS 0
#define G_T    512
#define G_BUF  55296
#define GEMM_SMEM_BYTES (512 + 2*55296)   // 111104 (Cs 66560 aliases tiles)

__device__ __forceinline__ void gemm_tile_ps(
    const __half* __restrict__ Ahg, const __half* __restrict__ Alg,
    const __half* __restrict__ Bhg,
    uint32_t smb, int tid, float* Cs) {
    const int wid = tid >> 5, lane = tid & 31;
    const int gr = lane >> 2, tg = lane & 3;
    const int wm = (wid >> 2) * 64;
    const int wn = (wid & 3) * 32;
    const int arow = lane & 15, acol = (lane >> 4) * 8;
    const int b_roff = (((lane >> 3) >> 1) & 1) * 8 + (lane & 7);
    const int b_koff = ((lane >> 3) & 1) * 8;

    float acc[4][4][4] = {};

    {
        uint32_t base = smb + G_T;
#pragma unroll
        for (int it = 0; it < 12; ++it) {
            int id = it * 256 + tid;
            int tile = id >> 10, idx = id & 1023;
            int rr = idx >> 3, gg = idx & 7;
            const __half* src =
                (tile == 0 ? Ahg : tile == 1 ? Alg : Bhg) +
                (size_t)rr * DM + gg * 8;
            cp16(base + tile * 18432 + rr * 144 + gg * 16, src);
        }
        CP_COMMIT();
    }

    for (int c = 0; c < 8; ++c) {
        const int cur = c & 1;
        if (c + 1 < 8) {
            const int k0 = (c + 1) * 64;
            uint32_t base = smb + G_T + (cur ^ 1) * G_BUF;
#pragma unroll
            for (int it = 0; it < 12; ++it) {
                int id = it * 256 + tid;
                int tile = id >> 10, idx = id & 1023;
                int rr = idx >> 3, gg = idx & 7;
                const __half* src =
                    (tile == 0 ? Ahg : tile == 1 ? Alg : Bhg)
                    + (size_t)rr * DM + k0 + gg * 8;
                cp16(base + tile * 18432 + rr * 144 + gg * 16, src);
            }
            CP_COMMIT();
            CP_WAIT1();
        } else {
            CP_WAIT0();
        }
        __syncthreads();

        const uint32_t base = smb + G_T + cur * G_BUF;
#pragma unroll
        for (int ks = 0; ks < 4; ++ks) {
            const int cc = ks * 16;
            uint32_t ahi[4][4], alo[4][4];
#pragma unroll
            for (int mt = 0; mt < 4; ++mt) {
                uint32_t aadr =
                    base + ((wm + mt * 16 + arow) * LDTG + cc + acol) * 2;
                ldm_x4(ahi[mt], aadr);
                ldm_x4(alo[mt], aadr + 18432);
            }
#pragma unroll
            for (int pp = 0; pp < 2; ++pp) {
                uint32_t bh4[4];
                uint32_t badr = base + 36864 +
                    ((wn + pp * 16 + b_roff) * LDTG + cc + b_koff) * 2;
                ldm_x4(bh4, badr);
#pragma unroll
                for (int q = 0; q < 2; ++q) {
                    int nt = 2 * pp + q;
                    uint32_t bh2[2] = {bh4[2 * q], bh4[2 * q + 1]};
#pragma unroll
                    for (int mt = 0; mt < 4; ++mt) {
                        mma_f16(acc[mt][nt], ahi[mt], bh2);
                        mma_f16(acc[mt][nt], alo[mt], bh2);
                    }
                }
            }
        }
        __syncthreads();
    }

#pragma unroll
    for (int mt = 0; mt < 4; ++mt)
#pragma unroll
        for (int nt = 0; nt < 4; ++nt) {
            int r  = wm + mt * 16 + gr;
            int cl = wn + nt * 8 + tg * 2;
            Cs[cl * CS_LD + r]           = acc[mt][nt][0];
            Cs[(cl + 1) * CS_LD + r]     = acc[mt][nt][1];
            Cs[cl * CS_LD + r + 8]       = acc[mt][nt][2];
            Cs[(cl + 1) * CS_LD + r + 8] = acc[mt][nt][3];
        }
    __syncthreads();
}

// ===========================================================================
// Kernel 2: QKV projections. grid = (64, 4, 3), block 256.
// Q pre-scaled by g_scale[h]/sqrt(512), stored (hi,lo) fp16.
// K row-major fp16 hi-only; V transposed (b,h,d,s) fp16 hi-only.
// ===========================================================================
__global__ __launch_bounds__(256) void qkv_mm_kernel_b(
    const float* __restrict__ bq, const float* __restrict__ bk,
    const float* __restrict__ bv) {
    extern __shared__ char sm[];
    const uint32_t smb = smem_u32(sm);
    const int tid = threadIdx.x;
    const int row0 = blockIdx.x * 128;
    const int n0   = blockIdx.y * 128;
    const int which = blockIdx.z;
    const float* bias = (which == 0) ? bq : (which == 1) ? bk : bv;
    float* bsm = (float*)(sm + G_BIAS);
    if (tid < 128) bsm[tid] = bias[n0 + tid];

    float* Cs = (float*)(sm + G_T);
    gemm_tile_ps(g_xhi + (size_t)row0 * DM, g_xlo + (size_t)row0 * DM,
                 g_wh + (size_t)which * DM * DM + (size_t)n0 * DM,
                 smb, tid, Cs);

    const int b   = row0 >> 11;
    const int s_b = row0 & (SEQ - 1);
    if (which == 0) {
        const int d0base = n0 >> 3;
#pragma unroll
        for (int it = 0; it < 16; ++it) {
            int id  = it * 256 + tid;
            int g   = id & 3;
            int h   = (id >> 2) & 7;
            int row = id >> 5;
            float qs = g_scale[h] * 0.04419417382415922f;
            float v[4];
#pragma unroll
            for (int u = 0; u < 4; ++u) {
                int j = h + 32 * g + 8 * u;
                v[u] = (Cs[j * CS_LD + row] + bsm[j]) * qs;
            }
            int s  = s_b + row;
            int d0 = d0base + 4 * g;
            size_t off = ((size_t)((b * NH + h) * SEQ + s)) * HD + d0;
            uint32_t h0, l0, h1, l1;
            split2h(v[0], v[1], h0, l0);
            split2h(v[2], v[3], h1, l1);
            *(uint2*)(g_qhi + off) = make_uint2(h0, h1);
            *(uint2*)(g_qlo + off) = make_uint2(l0, l1);
        }
    } else if (which == 1) {
        const int d0base = n0 >> 3;
#pragma unroll
        for (int it = 0; it < 16; ++it) {
            int id  = it * 256 + tid;
            int g   = id & 3;
            int h   = (id >> 2) & 7;
            int row = id >> 5;
            float v[4];
#pragma unroll
            for (int u = 0; u < 4; ++u) {
                int j = h + 32 * g + 8 * u;
                v[u] = Cs[j * CS_LD + row] + bsm[j];
            }
            int s  = s_b + row;
            int d0 = d0base + 4 * g;
            size_t off = ((size_t)((b * NH + h) * SEQ + s)) * HD + d0;
            *(uint2*)(g_kh + off) =
                make_uint2(pack2h(v[0], v[1]), pack2h(v[2], v[3]));
        }
    } else {
        // V transposed: vt[(b*NH+h)*HD + d][s], fp16 hi-only
#pragma unroll
        for (int it = 0; it < 16; ++it) {
            int id   = it * 256 + tid;
            int rblk = id & 31;
            int j    = id >> 5;
            int wr   = n0 + j;
            int h    = wr & 7;
            int d    = wr >> 3;
            float bj = bsm[j];
            float2 c0 = *(float2*)&Cs[j * CS_LD + rblk * 4];
            float2 c1 = *(float2*)&Cs[j * CS_LD + rblk * 4 + 2];
            size_t off =
                ((size_t)((b * NH + h) * HD + d)) * SEQ + s_b + rblk * 4;
            *(uint2*)(g_vth + off) =
                make_uint2(pack2h(c0.x + bj, c0.y + bj),
                           pack2h(c1.x + bj, c1.y + bj));
        }
    }
}

// ===========================================================================
// Kernel 4: output projection. grid = (64, 4), block 256. fp32 out.
// ===========================================================================
__global__ __launch_bounds__(256) void oproj_mm_kernel(
    const float* __restrict__ bp, float* __restrict__ out) {
    extern __shared__ char sm[];
    const uint32_t smb = smem_u32(sm);
    const int tid = threadIdx.x;
    const int row0 = blockIdx.x * 128;
    const int n0   = blockIdx.y * 128;

    float* bsm = (float*)(sm + G_BIAS);
    if (tid < 128) bsm[tid] = bp[n0 + tid];
    float* Cs = (float*)(sm + G_T);

    gemm_tile_ps(g_ohi + (size_t)row0 * DM, g_olo + (size_t)row0 * DM,
                 g_wh + (size_t)3 * DM * DM + (size_t)n0 * DM,
                 smb, tid, Cs);

#pragma unroll
    for (int it = 0; it < 16; ++it) {
        int id  = it * 256 + tid;
        int q4  = id & 31;
        int row = id >> 5;
        float v[4];
#pragma unroll
        for (int u = 0; u < 4; ++u) {
            int j = 4 * q4 + u;
            v[u] = Cs[j * CS_LD + row] + bsm[j];
        }
        *(float4*)(out + (size_t)(row0 + row) * DM + n0 + 4 * q4) =
            make_float4(v[0], v[1], v[2], v[3]);
    }
}

// ===========================================================================
// Kernel 3: flash attention, fp16 2-term, no-max softmax, cp.async
// double-buffered, ldmatrix. grid = (16, 32), block 256.
// smem: sg 2x192 f32 @0; tiles @1536, 2 buffers of Kh(9216)+Vth(9216).
// Q staging (hi 18432 + lo 18432 = 36864) reuses the tiles region.
// ===========================================================================
#define ALDT 72
#define ATT_SG 0
#define ATT_T  1536
#define ATT_BUF 18432
#define ATTN_SMEM_BYTES (1536 + 2*18432)   // 38400

__global__ __launch_bounds__(256) void attn_mm_kernel() {
    extern __shared__ char sm[];
    const uint32_t smb = smem_u32(sm);
    const int tid = threadIdx.x, wid = tid >> 5, lane = tid & 31;
    const int gr = lane >> 2, tg = lane & 3;
    const int b_roff = (((lane >> 3) >> 1) & 1) * 8 + (lane & 7);
    const int b_koff = ((lane >> 3) & 1) * 8;
    const int bh = blockIdx.y, b = bh >> 3, h = bh & 7;
    const int q0 = blockIdx.x * 128;
    const __half* Qh = g_qhi + (size_t)bh * SEQ * HD;
    const __half* Ql = g_qlo + (size_t)bh * SEQ * HD;
    const __half* Kh = g_kh  + (size_t)bh * SEQ * HD;
    const __half* Vh = g_vth + (size_t)bh * HD * SEQ;

    // ---- stage Q tile, lift fragments (region reused by tiles afterwards)
    uint32_t qhi[4][4], qlo[4][4];
    {
        __half* Qshi = (__half*)(sm + ATT_T);
        __half* Qslo = (__half*)(sm + ATT_T + 18432);
#pragma unroll
        for (int it = 0; it < 8; ++it) {
            int id = it * 256 + tid;
            int arr = id >> 10, rr = (id >> 3) & 127, gg = id & 7;
            const __half* src =
                (arr ? Ql : Qh) + (size_t)(q0 + rr) * HD + gg * 8;
            *(uint4*)((arr ? Qslo : Qshi) + rr * ALDT + gg * 8) =
                *(const uint4*)src;
        }
        __syncthreads();
        const int arow = lane & 15, acol = (lane >> 4) * 8;
        uint32_t qa = smb + ATT_T + ((wid * 16 + arow) * ALDT + acol) * 2;
#pragma unroll
        for (int ks = 0; ks < 4; ++ks) {
            ldm_x4(qhi[ks], qa + ks * 32);
            ldm_x4(qlo[ks], qa + ks * 32 + 18432);
        }
        __syncthreads();
    }

    float l0r = 0.0f, l1r = 0.0f;
    float Oa[8][4] = {};
    const int qi0 = wid * 16 + gr;

    // prologue: issue tile 0 into buf 0
    {
        uint32_t base = smb + ATT_T;
#pragma unroll
        for (int it = 0; it < 4; ++it) {
            int id = it * 256 + tid;
            int tile = id >> 9, idx = id & 511;
            int rr = idx >> 3, gg = idx & 7;
            const __half* src = tile ? (Vh + (size_t)rr * SEQ + gg * 8)
                                     : (Kh + (size_t)rr * HD + gg * 8);
            cp16(base + tile * 9216 + rr * 144 + gg * 16, src);
        }
        if (tid < 192)
            cp4(smb + ATT_SG + tid * 4,
                &g_sig[h * RPE_LEN + q0 + 1984 + tid]);
        CP_COMMIT();
    }

    for (int kt = 0; kt < 32; ++kt) {
        const int cur = kt & 1;
        if (kt + 1 < 32) {
            const int k0n = (kt + 1) * 64;
            uint32_t base = smb + ATT_T + (cur ^ 1) * ATT_BUF;
#pragma unroll
            for (int it = 0; it < 4; ++it) {
                int id = it * 256 + tid;
                int tile = id >> 9, idx = id & 511;
                int rr = idx >> 3, gg = idx & 7;
                const __half* src =
                    tile ? (Vh + (size_t)rr * SEQ + k0n + gg * 8)
                         : (Kh + (size_t)(k0n + rr) * HD + gg * 8);
                cp16(base + tile * 9216 + rr * 144 + gg * 16, src);
            }
            if (tid < 192)
                cp4(smb + ATT_SG + (cur ^ 1) * 768 + tid * 4,
                    &g_sig[h * RPE_LEN + q0 - k0n + 1984 + tid]);
            CP_COMMIT();
            CP_WAIT1();
        } else {
            CP_WAIT0();
        }
        __syncthreads();

        const uint32_t kbase = smb + ATT_T + cur * ATT_BUF;
        const float* sgp = (const float*)(sm + ATT_SG + cur * 768);

        // ---- S = Q K^T (2-term: Qhi*Kh + Qlo*Kh)
        float p[8][4] = {};
#pragma unroll
        for (int ks = 0; ks < 4; ++ks) {
            const int cc = ks * 16;
#pragma unroll
            for (int pp = 0; pp < 4; ++pp) {
                uint32_t bh4[4];
                uint32_t adr =
                    kbase + ((pp * 16 + b_roff) * ALDT + cc + b_koff) * 2;
                ldm_x4(bh4, adr);
#pragma unroll
                for (int q = 0; q < 2; ++q) {
                    int nt = 2 * pp + q;
                    uint32_t bh2[2] = {bh4[2 * q], bh4[2 * q + 1]};
                    mma_f16(p[nt], qhi[ks], bh2);
                    mma_f16(p[nt], qlo[ks], bh2);
                }
            }
        }

        // ---- no-max softmax: p = exp(s) * expsig(bias); accumulate l
#pragma unroll
        for (int nt = 0; nt < 8; ++nt) {
            int kj = nt * 8 + tg * 2;
            p[nt][0] = __expf(p[nt][0]) * sgp[qi0 - kj + 63];
            p[nt][1] = __expf(p[nt][1]) * sgp[qi0 - kj + 62];
            p[nt][2] = __expf(p[nt][2]) * sgp[qi0 - kj + 71];
            p[nt][3] = __expf(p[nt][3]) * sgp[qi0 - kj + 70];
            l0r += p[nt][0] + p[nt][1];
            l1r += p[nt][2] + p[nt][3];
        }

        // ---- pack P into split fp16 A-fragments (register-only)
        uint32_t phi[4][4], plo[4][4];
#pragma unroll
        for (int ks2 = 0; ks2 < 4; ++ks2) {
            int ntA = 2 * ks2, ntB = 2 * ks2 + 1;
            split2h(p[ntA][0], p[ntA][1], phi[ks2][0], plo[ks2][0]);
            split2h(p[ntA][2], p[ntA][3], phi[ks2][1], plo[ks2][1]);
            split2h(p[ntB][0], p[ntB][1], phi[ks2][2], plo[ks2][2]);
            split2h(p[ntB][2], p[ntB][3], phi[ks2][3], plo[ks2][3]);
        }

        // ---- O += P V (2-term: Phi*Vh + Plo*Vh)
#pragma unroll
        for (int ks2 = 0; ks2 < 4; ++ks2) {
            const int cc = ks2 * 16;
#pragma unroll
            for (int pp = 0; pp < 4; ++pp) {
                uint32_t vh4[4];
                uint32_t adr = kbase + 9216 +
                    ((pp * 16 + b_roff) * ALDT + cc + b_koff) * 2;
                ldm_x4(vh4, adr);
#pragma unroll
                for (int q = 0; q < 2; ++q) {
                    int nt = 2 * pp + q;
                    uint32_t vh2[2] = {vh4[2 * q], vh4[2 * q + 1]};
                    mma_f16(Oa[nt], phi[ks2], vh2);
                    mma_f16(Oa[nt], plo[ks2], vh2);
                }
            }
        }
        __syncthreads();
    }

    // ---- single final row-sum reduction across the 4 tg lanes
#pragma unroll
    for (int off = 1; off <= 2; off <<= 1) {
        l0r += __shfl_xor_sync(0xffffffffu, l0r, off);
        l1r += __shfl_xor_sync(0xffffffffu, l1r, off);
    }

    // ---- normalize, write split-fp16 concat-head output
    float inv0 = 1.0f / l0r, inv1 = 1.0f / l1r;
    int qrow = q0 + qi0;
#pragma unroll
    for (int nt = 0; nt < 8; ++nt) {
        int col = h * HD + nt * 8 + tg * 2;
        size_t off0 = (size_t)(b * SEQ + qrow) * DM + col;
        size_t off1 = (size_t)(b * SEQ + qrow + 8) * DM + col;
        uint32_t hp, lp;
        split2h(Oa[nt][0] * inv0, Oa[nt][1] * inv0, hp, lp);
        *(uint32_t*)(g_ohi + off0) = hp;
        *(uint32_t*)(g_olo + off0) = lp;
        split2h(Oa[nt][2] * inv1, Oa[nt][3] * inv1, hp, lp);
        *(uint32_t*)(g_ohi + off1) = hp;
        *(uint32_t*)(g_olo + off1) = lp;
    }
}

// ---------------------------------------------------------------------------
extern "C" void kernel_launch(void* const* d_in, const int* in_sizes, int n_in,
                              void* d_out, int out_size) {
    (void)in_sizes; (void)n_in; (void)out_size;
    const float* query = (const float*)d_in[0];
    const float* Wq = (const float*)d_in[1];
    const float* bq = (const float*)d_in[2];
    const float* Wk = (const float*)d_in[3];
    const float* bk = (const float*)d_in[4];
    const float* Wv = (const float*)d_in[5];
    const float* bv = (const float*)d_in[6];
    const float* Wp = (const float*)d_in[7];
    const float* bp = (const float*)d_in[8];
    const float* ls = (const float*)d_in[9];
    const float* rpe = (const float*)d_in[10];

    cudaFuncSetAttribute(qkv_mm_kernel_b,
                         cudaFuncAttributeMaxDynamicSharedMemorySize,
                         GEMM_SMEM_BYTES);
    cudaFuncSetAttribute(oproj_mm_kernel,
                         cudaFuncAttributeMaxDynamicSharedMemorySize,
                         GEMM_SMEM_BYTES);
    cudaFuncSetAttribute(attn_mm_kernel,
                         cudaFuncAttributeMaxDynamicSharedMemorySize,
                         ATTN_SMEM_BYTES);

    prep_kernel<<<(NH * RPE_LEN + 255) / 256, 256>>>(rpe, ls);
    split_x_kernel<<<ROWS * DM / 4 / 256, 256>>>((const float4*)query);
    conv_w_kernel<<<dim3(DM * DM / 4 / 256, 4), 256>>>(
        (const float4*)Wq, (const float4*)Wk,
        (const float4*)Wv, (const float4*)Wp);

    qkv_mm_kernel_b<<<dim3(ROWS / 128, DM / 128, 3), 256, GEMM_SMEM_BYTES>>>(
        bq, bk, bv);
    attn_mm_kernel<<<dim3(SEQ / 128, BATCH * NH), 256, ATTN_SMEM_BYTES>>>();
    oproj_mm_kernel<<<dim3(ROWS / 128, DM / 128), 256, GEMM_SMEM_BYTES>>>(
        bp, (float*)d_out);
}

// round 17
// speedup vs baseline: 2.3949x; 1.1962x over previous
#include <cuda_runtime.h>
#include <cuda_fp16.h>
#include <math.h>
#include <stdint.h>

#define BATCH 4
#define SEQ 2048
#define DM 512
#define NH 8
#define HD 64
#define ROWS (BATCH*SEQ)
#define RPE_LEN (2*SEQ-1)
#define QKV_ELEMS (BATCH*NH*SEQ*HD)

// --------- static device scratch (no allocations allowed) ------------------
__device__ __half g_xhi[ROWS*DM], g_xlo[ROWS*DM];   // X (hi,lo) fp16
__device__ __half g_wh[4*DM*DM];                    // Wq,Wk,Wv,Wp fp16
__device__ __half g_qhi[QKV_ELEMS], g_qlo[QKV_ELEMS]; // Q (hi,lo)
__device__ __half g_kh[QKV_ELEMS];                  // K fp16 (B-side)
__device__ __half g_vth[QKV_ELEMS];                 // V^T (b,h,d,s) fp16
__device__ __half g_oh[ROWS*DM];                    // attn out fp16 hi-only
__device__ float g_sig[NH*RPE_LEN];                 // exp(sigmoid(rpe))
__device__ float g_scale[NH];

// ===========================================================================
// helpers
// ===========================================================================
__device__ __forceinline__ uint32_t smem_u32(const void* p) {
    uint32_t a;
    asm("{ .reg .u64 t; cvta.to.shared.u64 t, %1; cvt.u32.u64 %0, t; }"
        : "=r"(a) : "l"(p));
    return a;
}
__device__ __forceinline__ void mma_f16(float d[4], const uint32_t a[4],
                                        const uint32_t b[2]) {
    asm volatile(
        "mma.sync.aligned.m16n8k16.row.col.f32.f16.f16.f32 "
        "{%0,%1,%2,%3}, {%4,%5,%6,%7}, {%8,%9}, {%0,%1,%2,%3};"
        : "+f"(d[0]), "+f"(d[1]), "+f"(d[2]), "+f"(d[3])
        : "r"(a[0]), "r"(a[1]), "r"(a[2]), "r"(a[3]), "r"(b[0]), "r"(b[1]));
}
__device__ __forceinline__ void ldm_x4(uint32_t r[4], uint32_t a) {
    asm volatile(
        "ldmatrix.sync.aligned.m8n8.x4.shared.b16 {%0,%1,%2,%3}, [%4];"
        : "=r"(r[0]), "=r"(r[1]), "=r"(r[2]), "=r"(r[3]) : "r"(a));
}
__device__ __forceinline__ uint32_t pack2h(float x0, float x1) {
    __half2 h = __floats2half2_rn(x0, x1);
    return *(uint32_t*)&h;
}
__device__ __forceinline__ void split2h(float x0, float x1,
                                        uint32_t& hp, uint32_t& lp) {
    hp = pack2h(x0, x1);
    __half2 h = *(__half2*)&hp;
    float2 hf = __half22float2(h);
    lp = pack2h(x0 - hf.x, x1 - hf.y);
}
__device__ __forceinline__ void cp16(uint32_t dst, const void* src) {
    asm volatile("cp.async.cg.shared.global [%0], [%1], 16;"
                 :: "r"(dst), "l"(src));
}
__device__ __forceinline__ void cp4(uint32_t dst, const void* src) {
    asm volatile("cp.async.ca.shared.global [%0], [%1], 4;"
                 :: "r"(dst), "l"(src));
}
#define CP_COMMIT() asm volatile("cp.async.commit_group;" ::: "memory")
#define CP_WAIT1()  asm volatile("cp.async.wait_group 1;" ::: "memory")
#define CP_WAIT0()  asm volatile("cp.async.wait_group 0;" ::: "memory")

// ===========================================================================
// Kernel 0a: exp(sigmoid(rpe)) table + per-head scale
// ===========================================================================
__global__ void prep_kernel(const float* __restrict__ rpe,
                            const float* __restrict__ ls) {
    int i = blockIdx.x * blockDim.x + threadIdx.x;
    if (i < NH * RPE_LEN) {
        int hh = i % NH;
        int p  = i / NH;
        float x = rpe[p * NH + hh];
        float sg = 1.0f / (1.0f + __expf(-x));
        g_sig[hh * RPE_LEN + p] = __expf(sg);
    }
    if (i < NH) g_scale[i] = __expf(fminf(ls[i], 4.6051701859880914f));
}

// ===========================================================================
// Kernel 0b: X fp32 -> (hi, lo) fp16 split
// ===========================================================================
__global__ void split_x_kernel(const float4* __restrict__ src) {
    int i = blockIdx.x * blockDim.x + threadIdx.x;
    float4 f = src[i];
    uint32_t h0, l0, h1, l1;
    split2h(f.x, f.y, h0, l0);
    split2h(f.z, f.w, h1, l1);
    ((uint2*)g_xhi)[i] = make_uint2(h0, h1);
    ((uint2*)g_xlo)[i] = make_uint2(l0, l1);
}

// ===========================================================================
// Kernel 0c: W fp32 -> fp16 (hi only). grid (256, 4).
// ===========================================================================
__global__ void conv_w_kernel(const float4* __restrict__ w0,
                              const float4* __restrict__ w1,
                              const float4* __restrict__ w2,
                              const float4* __restrict__ w3) {
    int i = blockIdx.x * blockDim.x + threadIdx.x;
    int which = blockIdx.y;
    const float4* w = (which == 0) ? w0 : (which == 1) ? w1
                     : (which == 2) ? w2 : w3;
    float4 f = w[i];
    ((uint2*)g_wh)[(size_t)which * (DM * DM / 4) + i] =
        make_uint2(pack2h(f.x, f.y), pack2h(f.z, f.w));
}

// ===========================================================================
// fp16 NT-term 128x128 GEMM tile: D = (Ahi [+ Alo]) * Bhi^T, K=512,
// chunks of 64, double-buffered cp.async, ldmatrix.
// 8 warps 2(m) x 4(n), warp tile 64x32.
// buffer (bytes): Ahi 0 [, Alo 18432], Bhi NT*18432  (LDTG=72)
// ===========================================================================
#define LDTG 72
#define CS_LD 130
#define G_BIAS 0
#define G_T    512

template <int NT>
__device__ __forceinline__ void gemm_tile_ps(
    const __half* __restrict__ Ahg, const __half* __restrict__ Alg,
    const __half* __restrict__ Bhg,
    uint32_t smb, int tid, float* Cs) {
    const int G_BUF = (NT + 1) * 18432;
    const int wid = tid >> 5, lane = tid & 31;
    const int gr = lane >> 2, tg = lane & 3;
    const int wm = (wid >> 2) * 64;
    const int wn = (wid & 3) * 32;
    const int arow = lane & 15, acol = (lane >> 4) * 8;
    const int b_roff = (((lane >> 3) >> 1) & 1) * 8 + (lane & 7);
    const int b_koff = ((lane >> 3) & 1) * 8;

    float acc[4][4][4] = {};

    {
        uint32_t base = smb + G_T;
#pragma unroll
        for (int it = 0; it < (NT + 1) * 4; ++it) {
            int id = it * 256 + tid;
            int tile = id >> 10, idx = id & 1023;
            int rr = idx >> 3, gg = idx & 7;
            const __half* src =
                (tile == 0) ? Ahg : (tile == NT) ? Bhg : Alg;
            cp16(base + tile * 18432 + rr * 144 + gg * 16,
                 src + (size_t)rr * DM + gg * 8);
        }
        CP_COMMIT();
    }

    for (int c = 0; c < 8; ++c) {
        const int cur = c & 1;
        if (c + 1 < 8) {
            const int k0 = (c + 1) * 64;
            uint32_t base = smb + G_T + (cur ^ 1) * G_BUF;
#pragma unroll
            for (int it = 0; it < (NT + 1) * 4; ++it) {
                int id = it * 256 + tid;
                int tile = id >> 10, idx = id & 1023;
                int rr = idx >> 3, gg = idx & 7;
                const __half* src =
                    (tile == 0) ? Ahg : (tile == NT) ? Bhg : Alg;
                cp16(base + tile * 18432 + rr * 144 + gg * 16,
                     src + (size_t)rr * DM + k0 + gg * 8);
            }
            CP_COMMIT();
            CP_WAIT1();
        } else {
            CP_WAIT0();
        }
        __syncthreads();

        const uint32_t base = smb + G_T + cur * G_BUF;
#pragma unroll
        for (int ks = 0; ks < 4; ++ks) {
            const int cc = ks * 16;
            uint32_t ahi[4][4], alo[4][4];
#pragma unroll
            for (int mt = 0; mt < 4; ++mt) {
                uint32_t aadr =
                    base + ((wm + mt * 16 + arow) * LDTG + cc + acol) * 2;
                ldm_x4(ahi[mt], aadr);
                if (NT == 2) ldm_x4(alo[mt], aadr + 18432);
            }
#pragma unroll
            for (int pp = 0; pp < 2; ++pp) {
                uint32_t bh4[4];
                uint32_t badr = base + NT * 18432 +
                    ((wn + pp * 16 + b_roff) * LDTG + cc + b_koff) * 2;
                ldm_x4(bh4, badr);
#pragma unroll
                for (int q = 0; q < 2; ++q) {
                    int nt = 2 * pp + q;
                    uint32_t bh2[2] = {bh4[2 * q], bh4[2 * q + 1]};
#pragma unroll
                    for (int mt = 0; mt < 4; ++mt) {
                        mma_f16(acc[mt][nt], ahi[mt], bh2);
                        if (NT == 2) mma_f16(acc[mt][nt], alo[mt], bh2);
                    }
                }
            }
        }
        __syncthreads();
    }

#pragma unroll
    for (int mt = 0; mt < 4; ++mt)
#pragma unroll
        for (int nt = 0; nt < 4; ++nt) {
            int r  = wm + mt * 16 + gr;
            int cl = wn + nt * 8 + tg * 2;
            Cs[cl * CS_LD + r]           = acc[mt][nt][0];
            Cs[(cl + 1) * CS_LD + r]     = acc[mt][nt][1];
            Cs[cl * CS_LD + r + 8]       = acc[mt][nt][2];
            Cs[(cl + 1) * CS_LD + r + 8] = acc[mt][nt][3];
        }
    __syncthreads();
}

#define QKV_SMEM_BYTES   (512 + 2*55296)   // NT=2: 111104
#define OPROJ_SMEM_BYTES (512 + 2*36864)   // NT=1: 74240

// ===========================================================================
// Kernel 2: QKV projections. grid = (64, 4, 3), block 256.
// Q pre-scaled by g_scale[h]/sqrt(512), stored (hi,lo) fp16.
// K row-major fp16 hi-only; V transposed (b,h,d,s) fp16 hi-only.
// ===========================================================================
__global__ __launch_bounds__(256) void qkv_mm_kernel_b(
    const float* __restrict__ bq, const float* __restrict__ bk,
    const float* __restrict__ bv) {
    extern __shared__ char sm[];
    const uint32_t smb = smem_u32(sm);
    const int tid = threadIdx.x;
    const int row0 = blockIdx.x * 128;
    const int n0   = blockIdx.y * 128;
    const int which = blockIdx.z;
    const float* bias = (which == 0) ? bq : (which == 1) ? bk : bv;
    float* bsm = (float*)(sm + G_BIAS);
    if (tid < 128) bsm[tid] = bias[n0 + tid];

    float* Cs = (float*)(sm + G_T);
    gemm_tile_ps<2>(g_xhi + (size_t)row0 * DM, g_xlo + (size_t)row0 * DM,
                    g_wh + (size_t)which * DM * DM + (size_t)n0 * DM,
                    smb, tid, Cs);

    const int b   = row0 >> 11;
    const int s_b = row0 & (SEQ - 1);
    if (which == 0) {
        const int d0base = n0 >> 3;
#pragma unroll
        for (int it = 0; it < 16; ++it) {
            int id  = it * 256 + tid;
            int g   = id & 3;
            int h   = (id >> 2) & 7;
            int row = id >> 5;
            float qs = g_scale[h] * 0.04419417382415922f;
            float v[4];
#pragma unroll
            for (int u = 0; u < 4; ++u) {
                int j = h + 32 * g + 8 * u;
                v[u] = (Cs[j * CS_LD + row] + bsm[j]) * qs;
            }
            int s  = s_b + row;
            int d0 = d0base + 4 * g;
            size_t off = ((size_t)((b * NH + h) * SEQ + s)) * HD + d0;
            uint32_t h0, l0, h1, l1;
            split2h(v[0], v[1], h0, l0);
            split2h(v[2], v[3], h1, l1);
            *(uint2*)(g_qhi + off) = make_uint2(h0, h1);
            *(uint2*)(g_qlo + off) = make_uint2(l0, l1);
        }
    } else if (which == 1) {
        const int d0base = n0 >> 3;
#pragma unroll
        for (int it = 0; it < 16; ++it) {
            int id  = it * 256 + tid;
            int g   = id & 3;
            int h   = (id >> 2) & 7;
            int row = id >> 5;
            float v[4];
#pragma unroll
            for (int u = 0; u < 4; ++u) {
                int j = h + 32 * g + 8 * u;
                v[u] = Cs[j * CS_LD + row] + bsm[j];
            }
            int s  = s_b + row;
            int d0 = d0base + 4 * g;
            size_t off = ((size_t)((b * NH + h) * SEQ + s)) * HD + d0;
            *(uint2*)(g_kh + off) =
                make_uint2(pack2h(v[0], v[1]), pack2h(v[2], v[3]));
        }
    } else {
        // V transposed: vt[(b*NH+h)*HD + d][s], fp16 hi-only
#pragma unroll
        for (int it = 0; it < 16; ++it) {
            int id   = it * 256 + tid;
            int rblk = id & 31;
            int j    = id >> 5;
            int wr   = n0 + j;
            int h    = wr & 7;
            int d    = wr >> 3;
            float bj = bsm[j];
            float2 c0 = *(float2*)&Cs[j * CS_LD + rblk * 4];
            float2 c1 = *(float2*)&Cs[j * CS_LD + rblk * 4 + 2];
            size_t off =
                ((size_t)((b * NH + h) * HD + d)) * SEQ + s_b + rblk * 4;
            *(uint2*)(g_vth + off) =
                make_uint2(pack2h(c0.x + bj, c0.y + bj),
                           pack2h(c1.x + bj, c1.y + bj));
        }
    }
}

// ===========================================================================
// Kernel 4: output projection, 1-term (A = attn out, fp16 hi-only).
// grid = (64, 4), block 256. fp32 out.
// ===========================================================================
__global__ __launch_bounds__(256) void oproj_mm_kernel(
    const float* __restrict__ bp, float* __restrict__ out) {
    extern __shared__ char sm[];
    const uint32_t smb = smem_u32(sm);
    const int tid = threadIdx.x;
    const int row0 = blockIdx.x * 128;
    const int n0   = blockIdx.y * 128;

    float* bsm = (float*)(sm + G_BIAS);
    if (tid < 128) bsm[tid] = bp[n0 + tid];
    float* Cs = (float*)(sm + G_T);

    gemm_tile_ps<1>(g_oh + (size_t)row0 * DM, (const __half*)nullptr,
                    g_wh + (size_t)3 * DM * DM + (size_t)n0 * DM,
                    smb, tid, Cs);

#pragma unroll
    for (int it = 0; it < 16; ++it) {
        int id  = it * 256 + tid;
        int q4  = id & 31;
        int row = id >> 5;
        float v[4];
#pragma unroll
        for (int u = 0; u < 4; ++u) {
            int j = 4 * q4 + u;
            v[u] = Cs[j * CS_LD + row] + bsm[j];
        }
        *(float4*)(out + (size_t)(row0 + row) * DM + n0 + 4 * q4) =
            make_float4(v[0], v[1], v[2], v[3]);
    }
}

// ===========================================================================
// Kernel 3: flash attention, fp16, no-max softmax, P hi-only in PV,
// cp.async double-buffered, ldmatrix. grid = (16, 32), block 256.
// smem: sg 2x192 f32 @0; tiles @1536, 2 buffers of Kh(9216)+Vth(9216).
// Q staging (hi 18432 + lo 18432) reuses the tiles region.
// ===========================================================================
#define ALDT 72
#define ATT_SG 0
#define ATT_T  1536
#define ATT_BUF 18432
#define ATTN_SMEM_BYTES (1536 + 2*18432)   // 38400

__global__ __launch_bounds__(256) void attn_mm_kernel() {
    extern __shared__ char sm[];
    const uint32_t smb = smem_u32(sm);
    const int tid = threadIdx.x, wid = tid >> 5, lane = tid & 31;
    const int gr = lane >> 2, tg = lane & 3;
    const int b_roff = (((lane >> 3) >> 1) & 1) * 8 + (lane & 7);
    const int b_koff = ((lane >> 3) & 1) * 8;
    const int bh = blockIdx.y, b = bh >> 3, h = bh & 7;
    const int q0 = blockIdx.x * 128;
    const __half* Qh = g_qhi + (size_t)bh * SEQ * HD;
    const __half* Ql = g_qlo + (size_t)bh * SEQ * HD;
    const __half* Kh = g_kh  + (size_t)bh * SEQ * HD;
    const __half* Vh = g_vth + (size_t)bh * HD * SEQ;

    // ---- stage Q tile, lift fragments (region reused by tiles afterwards)
    uint32_t qhi[4][4], qlo[4][4];
    {
        __half* Qshi = (__half*)(sm + ATT_T);
        __half* Qslo = (__half*)(sm + ATT_T + 18432);
#pragma unroll
        for (int it = 0; it < 8; ++it) {
            int id = it * 256 + tid;
            int arr = id >> 10, rr = (id >> 3) & 127, gg = id & 7;
            const __half* src =
                (arr ? Ql : Qh) + (size_t)(q0 + rr) * HD + gg * 8;
            *(uint4*)((arr ? Qslo : Qshi) + rr * ALDT + gg * 8) =
                *(const uint4*)src;
        }
        __syncthreads();
        const int arow = lane & 15, acol = (lane >> 4) * 8;
        uint32_t qa = smb + ATT_T + ((wid * 16 + arow) * ALDT + acol) * 2;
#pragma unroll
        for (int ks = 0; ks < 4; ++ks) {
            ldm_x4(qhi[ks], qa + ks * 32);
            ldm_x4(qlo[ks], qa + ks * 32 + 18432);
        }
        __syncthreads();
    }

    float l0r = 0.0f, l1r = 0.0f;
    float Oa[8][4] = {};
    const int qi0 = wid * 16 + gr;

    // prologue: issue tile 0 into buf 0
    {
        uint32_t base = smb + ATT_T;
#pragma unroll
        for (int it = 0; it < 4; ++it) {
            int id = it * 256 + tid;
            int tile = id >> 9, idx = id & 511;
            int rr = idx >> 3, gg = idx & 7;
            const __half* src = tile ? (Vh + (size_t)rr * SEQ + gg * 8)
                                     : (Kh + (size_t)rr * HD + gg * 8);
            cp16(base + tile * 9216 + rr * 144 + gg * 16, src);
        }
        if (tid < 192)
            cp4(smb + ATT_SG + tid * 4,
                &g_sig[h * RPE_LEN + q0 + 1984 + tid]);
        CP_COMMIT();
    }

    for (int kt = 0; kt < 32; ++kt) {
        const int cur = kt & 1;
        if (kt + 1 < 32) {
            const int k0n = (kt + 1) * 64;
            uint32_t base = smb + ATT_T + (cur ^ 1) * ATT_BUF;
#pragma unroll
            for (int it = 0; it < 4; ++it) {
                int id = it * 256 + tid;
                int tile = id >> 9, idx = id & 511;
                int rr = idx >> 3, gg = idx & 7;
                const __half* src =
                    tile ? (Vh + (size_t)rr * SEQ + k0n + gg * 8)
                         : (Kh + (size_t)(k0n + rr) * HD + gg * 8);
                cp16(base + tile * 9216 + rr * 144 + gg * 16, src);
            }
            if (tid < 192)
                cp4(smb + ATT_SG + (cur ^ 1) * 768 + tid * 4,
                    &g_sig[h * RPE_LEN + q0 - k0n + 1984 + tid]);
            CP_COMMIT();
            CP_WAIT1();
        } else {
            CP_WAIT0();
        }
        __syncthreads();

        const uint32_t kbase = smb + ATT_T + cur * ATT_BUF;
        const float* sgp = (const float*)(sm + ATT_SG + cur * 768);

        // ---- S = Q K^T (2-term: Qhi*Kh + Qlo*Kh)
        float p[8][4] = {};
#pragma unroll
        for (int ks = 0; ks < 4; ++ks) {
            const int cc = ks * 16;
#pragma unroll
            for (int pp = 0; pp < 4; ++pp) {
                uint32_t bh4[4];
                uint32_t adr =
                    kbase + ((pp * 16 + b_roff) * ALDT + cc + b_koff) * 2;
                ldm_x4(bh4, adr);
#pragma unroll
                for (int q = 0; q < 2; ++q) {
                    int nt = 2 * pp + q;
                    uint32_t bh2[2] = {bh4[2 * q], bh4[2 * q + 1]};
                    mma_f16(p[nt], qhi[ks], bh2);
                    mma_f16(p[nt], qlo[ks], bh2);
                }
            }
        }

        // ---- no-max softmax: p = exp(s) * expsig(bias); accumulate l
#pragma unroll
        for (int nt = 0; nt < 8; ++nt) {
            int kj = nt * 8 + tg * 2;
            p[nt][0] = __expf(p[nt][0]) * sgp[qi0 - kj + 63];
            p[nt][1] = __expf(p[nt][1]) * sgp[qi0 - kj + 62];
            p[nt][2] = __expf(p[nt][2]) * sgp[qi0 - kj + 71];
            p[nt][3] = __expf(p[nt][3]) * sgp[qi0 - kj + 70];
            l0r += p[nt][0] + p[nt][1];
            l1r += p[nt][2] + p[nt][3];
        }

        // ---- pack P into fp16 A-fragments (hi-only, register-only)
        uint32_t phi[4][4];
#pragma unroll
        for (int ks2 = 0; ks2 < 4; ++ks2) {
            int ntA = 2 * ks2, ntB = 2 * ks2 + 1;
            phi[ks2][0] = pack2h(p[ntA][0], p[ntA][1]);
            phi[ks2][1] = pack2h(p[ntA][2], p[ntA][3]);
            phi[ks2][2] = pack2h(p[ntB][0], p[ntB][1]);
            phi[ks2][3] = pack2h(p[ntB][2], p[ntB][3]);
        }

        // ---- O += P V (1-term: Phi*Vh)
#pragma unroll
        for (int ks2 = 0; ks2 < 4; ++ks2) {
            const int cc = ks2 * 16;
#pragma unroll
            for (int pp = 0; pp < 4; ++pp) {
                uint32_t vh4[4];
                uint32_t adr = kbase + 9216 +
                    ((pp * 16 + b_roff) * ALDT + cc + b_koff) * 2;
                ldm_x4(vh4, adr);
#pragma unroll
                for (int q = 0; q < 2; ++q) {
                    int nt = 2 * pp + q;
                    uint32_t vh2[2] = {vh4[2 * q], vh4[2 * q + 1]};
                    mma_f16(Oa[nt], phi[ks2], vh2);
                }
            }
        }
        __syncthreads();
    }

    // ---- single final row-sum reduction across the 4 tg lanes
#pragma unroll
    for (int off = 1; off <= 2; off <<= 1) {
        l0r += __shfl_xor_sync(0xffffffffu, l0r, off);
        l1r += __shfl_xor_sync(0xffffffffu, l1r, off);
    }

    // ---- normalize, write fp16 hi-only concat-head output
    float inv0 = 1.0f / l0r, inv1 = 1.0f / l1r;
    int qrow = q0 + qi0;
#pragma unroll
    for (int nt = 0; nt < 8; ++nt) {
        int col = h * HD + nt * 8 + tg * 2;
        size_t off0 = (size_t)(b * SEQ + qrow) * DM + col;
        size_t off1 = (size_t)(b * SEQ + qrow + 8) * DM + col;
        *(uint32_t*)(g_oh + off0) = pack2h(Oa[nt][0] * inv0, Oa[nt][1] * inv0);
        *(uint32_t*)(g_oh + off1) = pack2h(Oa[nt][2] * inv1, Oa[nt][3] * inv1);
    }
}

// ---------------------------------------------------------------------------
extern "C" void kernel_launch(void* const* d_in, const int* in_sizes, int n_in,
                              void* d_out, int out_size) {
    (void)in_sizes; (void)n_in; (void)out_size;
    const float* query = (const float*)d_in[0];
    const float* Wq = (const float*)d_in[1];
    const float* bq = (const float*)d_in[2];
    const float* Wk = (const float*)d_in[3];
    const float* bk = (const float*)d_in[4];
    const float* Wv = (const float*)d_in[5];
    const float* bv = (const float*)d_in[6];
    const float* Wp = (const float*)d_in[7];
    const float* bp = (const float*)d_in[8];
    const float* ls = (const float*)d_in[9];
    const float* rpe = (const float*)d_in[10];

    cudaFuncSetAttribute(qkv_mm_kernel_b,
                         cudaFuncAttributeMaxDynamicSharedMemorySize,
                         QKV_SMEM_BYTES);
    cudaFuncSetAttribute(oproj_mm_kernel,
                         cudaFuncAttributeMaxDynamicSharedMemorySize,
                         OPROJ_SMEM_BYTES);
    cudaFuncSetAttribute(attn_mm_kernel,
                         cudaFuncAttributeMaxDynamicSharedMemorySize,
                         ATTN_SMEM_BYTES);

    prep_kernel<<<(NH * RPE_LEN + 255) / 256, 256>>>(rpe, ls);
    split_x_kernel<<<ROWS * DM / 4 / 256, 256>>>((const float4*)query);
    conv_w_kernel<<<dim3(DM * DM / 4 / 256, 4), 256>>>(
        (const float4*)Wq, (const float4*)Wk,
        (const float4*)Wv, (const float4*)Wp);

    qkv_mm_kernel_b<<<dim3(ROWS / 128, DM / 128, 3), 256, QKV_SMEM_BYTES>>>(
        bq, bk, bv);
    attn_mm_kernel<<<dim3(SEQ / 128, BATCH * NH), 256, ATTN_SMEM_BYTES>>>();
    oproj_mm_kernel<<<dim3(ROWS / 128, DM / 128), 256, OPROJ_SMEM_BYTES>>>(
        bp, (float*)d_out);
}